// round 7
// baseline (speedup 1.0000x reference)
#include <cuda_runtime.h>
#include <cuda_bf16.h>

// ---------------------------------------------------------------------------
// GATnet 2-layer GAT, N=100000, E=1600000, IN=128, L1: 8x8 concat, ELU,
// L2: 1x40, log_softmax.
// R6: warp-per-node gather with edge-slot parallelism (4x/2x MLP + load
// balance), f32x2 packed FMA in the input GEMM, shuffle-based CSR scans.
// ---------------------------------------------------------------------------

#define N_CAP 100000
#define E_CAP 1600000
#define IN_F  128
#define HC1   64
#define H1    8
#define OUT2  40
#define NEG_SLOPE 0.2f

// Scratch (static device globals)
__device__ float4 g_h1[N_CAP * 16];        // [N][64]
__device__ float  g_asrc1[N_CAP * H1];
__device__ float  g_adst1[N_CAP * H1];
__device__ float  g_g2[N_CAP * OUT2];      // [N][40]
__device__ float  g_asrc2[N_CAP];
__device__ float  g_adst2[N_CAP];
__device__ int    g_esrc[E_CAP];           // CSR: src ids grouped by dst
__device__ int    g_deg[N_CAP];
__device__ int    g_rowptr[N_CAP];
__device__ int    g_cursor[N_CAP];
__device__ int    g_blksum[256];
__device__ int    g_is64;

__device__ __forceinline__ float lrelu(float v) { return v > 0.f ? v : NEG_SLOPE * v; }

__device__ __forceinline__ unsigned long long pk2(float lo, float hi) {
    unsigned long long r;
    asm("mov.b64 %0, {%1, %2};" : "=l"(r) : "f"(lo), "f"(hi));
    return r;
}
__device__ __forceinline__ void unpk2(float& lo, float& hi, unsigned long long v) {
    asm("mov.b64 {%0, %1}, %2;" : "=f"(lo), "=f"(hi) : "l"(v));
}
__device__ __forceinline__ unsigned long long ffma2(
    unsigned long long a, unsigned long long b, unsigned long long c) {
    unsigned long long d;
    asm("fma.rn.f32x2 %0, %1, %2, %3;" : "=l"(d) : "l"(a), "l"(b), "l"(c));
    return d;
}

// ---------------------------------------------------------------------------
// CSR construction
// ---------------------------------------------------------------------------
__global__ void k0_detect(const unsigned int* ei32, int nwords) {
    __shared__ int any_nz;
    if (threadIdx.x == 0) any_nz = 0;
    __syncthreads();
    int samples = 2048;
    if (samples * 2 > nwords) samples = nwords / 2;
    for (int i = threadIdx.x; i < samples; i += 256)
        if (ei32[2 * i + 1] != 0u) any_nz = 1;
    __syncthreads();
    if (threadIdx.x == 0) g_is64 = (any_nz == 0) ? 1 : 0;
}

__global__ __launch_bounds__(256) void k_zero(int N) {
    int i = blockIdx.x * 256 + threadIdx.x;
    if (i < N) g_deg[i] = 0;
}

__global__ __launch_bounds__(256) void k_hist(const void* ei, int E) {
    int i = blockIdx.x * 256 + threadIdx.x;
    if (i >= E) return;
    int dst = g_is64 ? (int)((const long long*)ei)[E + i] : ((const int*)ei)[E + i];
    atomicAdd(&g_deg[dst], 1);
}

// shuffle-based inclusive scan over 512 elements per block
__global__ __launch_bounds__(512) void k_scan1(int N) {
    __shared__ int wsum[16];
    int i = blockIdx.x * 512 + threadIdx.x;
    int v = (i < N) ? g_deg[i] : 0;
    int lane = threadIdx.x & 31, warp = threadIdx.x >> 5;
    int x = v;
#pragma unroll
    for (int o = 1; o < 32; o <<= 1) {
        int t = __shfl_up_sync(0xffffffffu, x, o);
        if (lane >= o) x += t;
    }
    if (lane == 31) wsum[warp] = x;
    __syncthreads();
    if (warp == 0) {
        int ws = (lane < 16) ? wsum[lane] : 0;
#pragma unroll
        for (int o = 1; o < 16; o <<= 1) {
            int t = __shfl_up_sync(0xffffffffu, ws, o);
            if (lane >= o) ws += t;
        }
        if (lane < 16) wsum[lane] = ws;
    }
    __syncthreads();
    int base = warp ? wsum[warp - 1] : 0;
    if (i < N) g_rowptr[i] = base + x - v;   // exclusive
    if (threadIdx.x == 511) g_blksum[blockIdx.x] = base + x;
}

// parallel exclusive scan over <=256 block sums
__global__ __launch_bounds__(256) void k_scan2(int nb) {
    __shared__ int wsum[8];
    int lane = threadIdx.x & 31, warp = threadIdx.x >> 5;
    int v = (threadIdx.x < nb) ? g_blksum[threadIdx.x] : 0;
    int x = v;
#pragma unroll
    for (int o = 1; o < 32; o <<= 1) {
        int t = __shfl_up_sync(0xffffffffu, x, o);
        if (lane >= o) x += t;
    }
    if (lane == 31) wsum[warp] = x;
    __syncthreads();
    if (warp == 0) {
        int ws = (lane < 8) ? wsum[lane] : 0;
#pragma unroll
        for (int o = 1; o < 8; o <<= 1) {
            int t = __shfl_up_sync(0xffffffffu, ws, o);
            if (lane >= o) ws += t;
        }
        if (lane < 8) wsum[lane] = ws;
    }
    __syncthreads();
    int base = warp ? wsum[warp - 1] : 0;
    if (threadIdx.x < nb) g_blksum[threadIdx.x] = base + x - v;   // exclusive
}

__global__ __launch_bounds__(256) void k_scan3(int N) {
    int i = blockIdx.x * 256 + threadIdx.x;
    if (i >= N) return;
    int r = g_rowptr[i] + g_blksum[i >> 9];
    g_rowptr[i] = r;
    g_cursor[i] = r;
}

__global__ __launch_bounds__(256) void k_scatter(const void* ei, int E) {
    int i = blockIdx.x * 256 + threadIdx.x;
    if (i >= E) return;
    int src, dst;
    if (g_is64) {
        src = (int)((const long long*)ei)[i];
        dst = (int)((const long long*)ei)[E + i];
    } else {
        src = ((const int*)ei)[i];
        dst = ((const int*)ei)[E + i];
    }
    int pos = atomicAdd(&g_cursor[dst], 1);
    g_esrc[pos] = src;
}

// ---------------------------------------------------------------------------
// K1: h1 = x @ W1; a_src1/a_dst1 = h1 . att. f32x2 packed FMA mainloop.
// Block: 256 thr -> 128 nodes x 64 outs. Thread: 2 nodes x 16 outs (8 pairs).
// ---------------------------------------------------------------------------
__global__ __launch_bounds__(256) void k1_gemm_attn(
    const float* __restrict__ x, const float* __restrict__ W1,
    const float* __restrict__ atts, const float* __restrict__ attd, int N)
{
    __shared__ __align__(16) float Ws[IN_F * HC1];   // 32KB
    __shared__ float s_as[HC1], s_ad[HC1];
    for (int i = threadIdx.x; i < IN_F * HC1; i += 256) Ws[i] = W1[i];
    if (threadIdx.x < HC1) { s_as[threadIdx.x] = atts[threadIdx.x]; s_ad[threadIdx.x] = attd[threadIdx.x]; }
    __syncthreads();

    const int jq = threadIdx.x & 3;
    const int j0 = jq * 16;
    const int pr = threadIdx.x >> 2;
    const long long n0 = (long long)blockIdx.x * 128 + pr * 2;
    const long long n1 = n0 + 1;
    const bool v0 = n0 < N, v1 = n1 < N;

    const float4* xp0 = (const float4*)(x + (v0 ? n0 : 0) * IN_F);
    const float4* xp1 = (const float4*)(x + (v1 ? n1 : 0) * IN_F);

    unsigned long long a0p[8], a1p[8];
    const unsigned long long Z = pk2(0.f, 0.f);
#pragma unroll
    for (int i = 0; i < 8; i++) { a0p[i] = Z; a1p[i] = Z; }

#pragma unroll 8
    for (int k4 = 0; k4 < IN_F / 4; k4++) {
        float4 xa = xp0[k4];
        float4 xb = xp1[k4];
        const float* wrow = &Ws[k4 * 4 * HC1 + j0];
#pragma unroll
        for (int kk = 0; kk < 4; kk++) {
            float xav = (&xa.x)[kk];
            float xbv = (&xb.x)[kk];
            unsigned long long xap = pk2(xav, xav);
            unsigned long long xbp = pk2(xbv, xbv);
#pragma unroll
            for (int jj = 0; jj < 4; jj++) {
                ulonglong2 w2 = *(const ulonglong2*)(wrow + kk * HC1 + jj * 4);
                a0p[jj*2+0] = ffma2(xap, w2.x, a0p[jj*2+0]);
                a0p[jj*2+1] = ffma2(xap, w2.y, a0p[jj*2+1]);
                a1p[jj*2+0] = ffma2(xbp, w2.x, a1p[jj*2+0]);
                a1p[jj*2+1] = ffma2(xbp, w2.y, a1p[jj*2+1]);
            }
        }
    }

    const int h0 = j0 >> 3;
#pragma unroll
    for (int sel = 0; sel < 2; sel++) {
        const bool valid = sel ? v1 : v0;
        if (!valid) continue;
        const long long n = sel ? n1 : n0;
        unsigned long long* ap = sel ? a1p : a0p;
        float acc[16];
#pragma unroll
        for (int i = 0; i < 8; i++) unpk2(acc[2*i], acc[2*i+1], ap[i]);

        float as0 = 0.f, ad0 = 0.f, as1 = 0.f, ad1 = 0.f;
#pragma unroll
        for (int c = 0; c < 8; c++) {
            as0 += acc[c]     * s_as[h0 * 8 + c];
            ad0 += acc[c]     * s_ad[h0 * 8 + c];
            as1 += acc[8 + c] * s_as[(h0 + 1) * 8 + c];
            ad1 += acc[8 + c] * s_ad[(h0 + 1) * 8 + c];
        }
        g_asrc1[n * H1 + h0]     = as0;  g_asrc1[n * H1 + h0 + 1] = as1;
        g_adst1[n * H1 + h0]     = ad0;  g_adst1[n * H1 + h0 + 1] = ad1;

        float4* hp = &g_h1[n * 16 + jq * 4];
#pragma unroll
        for (int q = 0; q < 4; q++)
            hp[q] = make_float4(acc[q*4+0], acc[q*4+1], acc[q*4+2], acc[q*4+3]);
    }
}

// ---------------------------------------------------------------------------
// KL1: fused layer-1 aggregate + normalize + ELU + h2@W2 + layer-2 attention.
// Warp per node (4 edge-slots x 8 heads); each warp walks 4 nodes.
// ---------------------------------------------------------------------------
__global__ __launch_bounds__(256) void kL1_gather(
    const float* __restrict__ W2, const float* __restrict__ b1,
    const float* __restrict__ atts2, const float* __restrict__ attd2, int N)
{
    __shared__ float W2s[HC1 * OUT2];   // 10.2KB
    __shared__ float b1s[HC1], as2s[OUT2], ad2s[OUT2];
    for (int i = threadIdx.x; i < HC1 * OUT2; i += 256) W2s[i] = W2[i];
    if (threadIdx.x < HC1) b1s[threadIdx.x] = b1[threadIdx.x];
    if (threadIdx.x < OUT2) { as2s[threadIdx.x] = atts2[threadIdx.x]; ad2s[threadIdx.x] = attd2[threadIdx.x]; }
    __syncthreads();

    const int lane = threadIdx.x & 31;
    const int r = lane & 7;        // head
    const int q = lane >> 3;       // edge slot 0..3
    const int warp = threadIdx.x >> 5;

#pragma unroll 1
    for (int it = 0; it < 4; it++) {
        const int n = blockIdx.x * 32 + warp * 4 + it;
        const int nc = (n < N) ? n : 0;

        const float adst = g_adst1[nc * H1 + r];
        const int beg = g_rowptr[nc];
        const int end = beg + g_deg[nc];

        float denom = 0.f;
        float acc[8] = {0.f,0.f,0.f,0.f,0.f,0.f,0.f,0.f};
        if (q == 0) {   // self-loop counted once
            float w = __expf(lrelu(g_asrc1[nc * H1 + r] + adst));
            denom = w;
            float4 a0 = g_h1[(long long)nc * 16 + r * 2];
            float4 a1 = g_h1[(long long)nc * 16 + r * 2 + 1];
            acc[0] = w*a0.x; acc[1] = w*a0.y; acc[2] = w*a0.z; acc[3] = w*a0.w;
            acc[4] = w*a1.x; acc[5] = w*a1.y; acc[6] = w*a1.z; acc[7] = w*a1.w;
        }

        for (int p = beg + q; p < end; p += 4) {
            int src = g_esrc[p];
            float wi = __expf(lrelu(g_asrc1[src * H1 + r] + adst));
            denom += wi;
            float4 v0 = g_h1[(long long)src * 16 + r * 2];
            float4 v1 = g_h1[(long long)src * 16 + r * 2 + 1];
            acc[0] += wi * v0.x; acc[1] += wi * v0.y; acc[2] += wi * v0.z; acc[3] += wi * v0.w;
            acc[4] += wi * v1.x; acc[5] += wi * v1.y; acc[6] += wi * v1.z; acc[7] += wi * v1.w;
        }

        // butterfly reduce across the 4 edge slots -> all lanes hold totals
#pragma unroll
        for (int o = 8; o <= 16; o <<= 1) {
            denom += __shfl_xor_sync(0xffffffffu, denom, o);
#pragma unroll
            for (int c = 0; c < 8; c++)
                acc[c] += __shfl_xor_sync(0xffffffffu, acc[c], o);
        }

        // h2 = elu(acc/denom + b1)
        float inv = 1.0f / denom;
        float h2r[8];
        {
            const float* bb = &b1s[r * 8];
#pragma unroll
            for (int c = 0; c < 8; c++) {
                float v = acc[c] * inv + bb[c];
                h2r[c] = v > 0.f ? v : expm1f(v);
            }
        }

        // g = h2 @ W2 (width-8 shuffle GEMM); lane r owns cols r, r+8, ..., r+32
        float acc2[5] = {0.f, 0.f, 0.f, 0.f, 0.f};
#pragma unroll
        for (int k = 0; k < HC1; k++) {
            float hk = __shfl_sync(0xffffffffu, h2r[k & 7], k >> 3, 8);
#pragma unroll
            for (int i = 0; i < 5; i++) acc2[i] += hk * W2s[k * OUT2 + r + 8 * i];
        }

        float as = 0.f, ad = 0.f;
#pragma unroll
        for (int i = 0; i < 5; i++) { as += acc2[i] * as2s[r + 8 * i]; ad += acc2[i] * ad2s[r + 8 * i]; }
#pragma unroll
        for (int o = 4; o; o >>= 1) {
            as += __shfl_xor_sync(0xffffffffu, as, o, 8);
            ad += __shfl_xor_sync(0xffffffffu, ad, o, 8);
        }

        if (q == 0 && n < N) {
            if (r == 0) { g_asrc2[n] = as; g_adst2[n] = ad; }
            float* gp = g_g2 + (long long)n * OUT2;
#pragma unroll
            for (int i = 0; i < 5; i++) gp[r + 8 * i] = acc2[i];
        }
    }
}

// ---------------------------------------------------------------------------
// KL2: fused layer-2 aggregate + normalize + bias + log_softmax.
// Warp per node: 2 edge-slots x 16 lanes (10 active carry one float4 each).
// ---------------------------------------------------------------------------
__global__ __launch_bounds__(256) void kL2_gather(
    const float* __restrict__ b2, float* __restrict__ out, int N)
{
    const int lane = threadIdx.x & 31;
    const int r = lane & 15;
    const int s = lane >> 4;       // edge slot 0..1
    const int n = blockIdx.x * 8 + (threadIdx.x >> 5);
    const int nc = (n < N) ? n : 0;
    const bool act = (r < 10);

    const float adst = g_adst2[nc];
    const int beg = g_rowptr[nc];
    const int end = beg + g_deg[nc];

    float denom = 0.f;
    float4 acc = make_float4(0.f, 0.f, 0.f, 0.f);
    if (s == 0) {   // self-loop once
        float w = __expf(lrelu(g_asrc2[nc] + adst));
        denom = w;
        if (act) {
            float4 g = ((const float4*)(g_g2 + (long long)nc * OUT2))[r];
            acc = make_float4(w * g.x, w * g.y, w * g.z, w * g.w);
        }
    }

    for (int p = beg + s; p < end; p += 2) {
        int src = g_esrc[p];
        float wi = __expf(lrelu(g_asrc2[src] + adst));
        denom += wi;
        if (act) {
            float4 g = ((const float4*)(g_g2 + (long long)src * OUT2))[r];
            acc.x += wi * g.x; acc.y += wi * g.y; acc.z += wi * g.z; acc.w += wi * g.w;
        }
    }

    // combine the two slots
    denom += __shfl_xor_sync(0xffffffffu, denom, 16);
    acc.x += __shfl_xor_sync(0xffffffffu, acc.x, 16);
    acc.y += __shfl_xor_sync(0xffffffffu, acc.y, 16);
    acc.z += __shfl_xor_sync(0xffffffffu, acc.z, 16);
    acc.w += __shfl_xor_sync(0xffffffffu, acc.w, 16);

    float inv = 1.0f / denom;
    float4 v = make_float4(-3.0e38f, -3.0e38f, -3.0e38f, -3.0e38f);
    if (act) {
        float4 bb = ((const float4*)b2)[r];
        v = make_float4(acc.x * inv + bb.x, acc.y * inv + bb.y,
                        acc.z * inv + bb.z, acc.w * inv + bb.w);
    }

    // log_softmax across the 10 active lanes (width-16 reductions)
    float m = fmaxf(fmaxf(v.x, v.y), fmaxf(v.z, v.w));
#pragma unroll
    for (int o = 8; o; o >>= 1) m = fmaxf(m, __shfl_xor_sync(0xffffffffu, m, o, 16));
    float sum = 0.f;
    if (act) sum = expf(v.x - m) + expf(v.y - m) + expf(v.z - m) + expf(v.w - m);
#pragma unroll
    for (int o = 8; o; o >>= 1) sum += __shfl_xor_sync(0xffffffffu, sum, o, 16);
    float lse = m + logf(sum);

    if (s == 0 && act && n < N) {
        float4 o4 = make_float4(v.x - lse, v.y - lse, v.z - lse, v.w - lse);
        ((float4*)(out + (long long)n * OUT2))[r] = o4;
    }
}

// ---------------------------------------------------------------------------
extern "C" void kernel_launch(void* const* d_in, const int* in_sizes, int n_in,
                              void* d_out, int out_size)
{
    const float* x     = (const float*)d_in[0];
    const void*  ei    = d_in[1];
    const float* W1    = (const float*)d_in[2];
    const float* atts1 = (const float*)d_in[3];
    const float* attd1 = (const float*)d_in[4];
    const float* b1    = (const float*)d_in[5];
    const float* W2    = (const float*)d_in[6];
    const float* atts2 = (const float*)d_in[7];
    const float* attd2 = (const float*)d_in[8];
    const float* b2    = (const float*)d_in[9];

    int N = in_sizes[0] / IN_F;
    int E = in_sizes[1] / 2;
    if (N > N_CAP) N = N_CAP;
    if (E > E_CAP) E = E_CAP;
    const int nb_scan = (N + 511) / 512;

    k0_detect<<<1, 256>>>((const unsigned int*)ei, 2 * E);
    k_zero<<<(N + 255) / 256, 256>>>(N);
    k_hist<<<(E + 255) / 256, 256>>>(ei, E);
    k_scan1<<<nb_scan, 512>>>(N);
    k_scan2<<<1, 256>>>(nb_scan);
    k_scan3<<<(N + 255) / 256, 256>>>(N);
    k_scatter<<<(E + 255) / 256, 256>>>(ei, E);

    k1_gemm_attn<<<(N + 127) / 128, 256>>>(x, W1, atts1, attd1, N);
    kL1_gather<<<(N + 31) / 32, 256>>>(W2, b1, atts2, attd2, N);
    kL2_gather<<<(N + 7) / 8, 256>>>(b2, (float*)d_out, N);
}

// round 8
// speedup vs baseline: 1.4477x; 1.4477x over previous
#include <cuda_runtime.h>
#include <cuda_bf16.h>

// ---------------------------------------------------------------------------
// GATnet 2-layer GAT, N=100000, E=1600000, IN=128, L1: 8x8 concat, ELU,
// L2: 1x40, log_softmax.
// R7: R5 structure (8 lanes/node kL1, 16 lanes/node kL2, node-parallel within
// warp) + 2x unrolled/software-pipelined gather loops for 2x MLP.
// ---------------------------------------------------------------------------

#define N_CAP 100000
#define E_CAP 1600000
#define IN_F  128
#define HC1   64
#define H1    8
#define OUT2  40
#define NEG_SLOPE 0.2f

// Scratch (static device globals)
__device__ float4 g_h1[N_CAP * 16];        // [N][64]
__device__ float  g_asrc1[N_CAP * H1];
__device__ float  g_adst1[N_CAP * H1];
__device__ float  g_g2[N_CAP * OUT2];      // [N][40]
__device__ float  g_asrc2[N_CAP];
__device__ float  g_adst2[N_CAP];
__device__ int    g_esrc[E_CAP];           // CSR: src ids grouped by dst
__device__ int    g_deg[N_CAP];
__device__ int    g_rowptr[N_CAP];
__device__ int    g_cursor[N_CAP];
__device__ int    g_blksum[256];
__device__ int    g_is64;

__device__ __forceinline__ float lrelu(float v) { return v > 0.f ? v : NEG_SLOPE * v; }

// ---------------------------------------------------------------------------
// CSR construction
// ---------------------------------------------------------------------------
__global__ void k0_detect(const unsigned int* ei32, int nwords) {
    __shared__ int any_nz;
    if (threadIdx.x == 0) any_nz = 0;
    __syncthreads();
    int samples = 2048;
    if (samples * 2 > nwords) samples = nwords / 2;
    for (int i = threadIdx.x; i < samples; i += 256)
        if (ei32[2 * i + 1] != 0u) any_nz = 1;
    __syncthreads();
    if (threadIdx.x == 0) g_is64 = (any_nz == 0) ? 1 : 0;
}

__global__ __launch_bounds__(256) void k_zero(int N) {
    int i = blockIdx.x * 256 + threadIdx.x;
    if (i < N) g_deg[i] = 0;
}

__global__ __launch_bounds__(256) void k_hist(const void* ei, int E) {
    int i = blockIdx.x * 256 + threadIdx.x;
    if (i >= E) return;
    int dst = g_is64 ? (int)((const long long*)ei)[E + i] : ((const int*)ei)[E + i];
    atomicAdd(&g_deg[dst], 1);
}

// shuffle-based inclusive scan over 512 elements per block
__global__ __launch_bounds__(512) void k_scan1(int N) {
    __shared__ int wsum[16];
    int i = blockIdx.x * 512 + threadIdx.x;
    int v = (i < N) ? g_deg[i] : 0;
    int lane = threadIdx.x & 31, warp = threadIdx.x >> 5;
    int x = v;
#pragma unroll
    for (int o = 1; o < 32; o <<= 1) {
        int t = __shfl_up_sync(0xffffffffu, x, o);
        if (lane >= o) x += t;
    }
    if (lane == 31) wsum[warp] = x;
    __syncthreads();
    if (warp == 0) {
        int ws = (lane < 16) ? wsum[lane] : 0;
#pragma unroll
        for (int o = 1; o < 16; o <<= 1) {
            int t = __shfl_up_sync(0xffffffffu, ws, o);
            if (lane >= o) ws += t;
        }
        if (lane < 16) wsum[lane] = ws;
    }
    __syncthreads();
    int base = warp ? wsum[warp - 1] : 0;
    if (i < N) g_rowptr[i] = base + x - v;   // exclusive
    if (threadIdx.x == 511) g_blksum[blockIdx.x] = base + x;
}

// parallel exclusive scan over <=256 block sums
__global__ __launch_bounds__(256) void k_scan2(int nb) {
    __shared__ int wsum[8];
    int lane = threadIdx.x & 31, warp = threadIdx.x >> 5;
    int v = (threadIdx.x < nb) ? g_blksum[threadIdx.x] : 0;
    int x = v;
#pragma unroll
    for (int o = 1; o < 32; o <<= 1) {
        int t = __shfl_up_sync(0xffffffffu, x, o);
        if (lane >= o) x += t;
    }
    if (lane == 31) wsum[warp] = x;
    __syncthreads();
    if (warp == 0) {
        int ws = (lane < 8) ? wsum[lane] : 0;
#pragma unroll
        for (int o = 1; o < 8; o <<= 1) {
            int t = __shfl_up_sync(0xffffffffu, ws, o);
            if (lane >= o) ws += t;
        }
        if (lane < 8) wsum[lane] = ws;
    }
    __syncthreads();
    int base = warp ? wsum[warp - 1] : 0;
    if (threadIdx.x < nb) g_blksum[threadIdx.x] = base + x - v;   // exclusive
}

__global__ __launch_bounds__(256) void k_scan3(int N) {
    int i = blockIdx.x * 256 + threadIdx.x;
    if (i >= N) return;
    int r = g_rowptr[i] + g_blksum[i >> 9];
    g_rowptr[i] = r;
    g_cursor[i] = r;
}

__global__ __launch_bounds__(256) void k_scatter(const void* ei, int E) {
    int i = blockIdx.x * 256 + threadIdx.x;
    if (i >= E) return;
    int src, dst;
    if (g_is64) {
        src = (int)((const long long*)ei)[i];
        dst = (int)((const long long*)ei)[E + i];
    } else {
        src = ((const int*)ei)[i];
        dst = ((const int*)ei)[E + i];
    }
    int pos = atomicAdd(&g_cursor[dst], 1);
    g_esrc[pos] = src;
}

// ---------------------------------------------------------------------------
// K1: h1 = x @ W1; a_src1/a_dst1 = h1 . att.  (R5 version, known good)
// ---------------------------------------------------------------------------
__global__ __launch_bounds__(256) void k1_gemm_attn(
    const float* __restrict__ x, const float* __restrict__ W1,
    const float* __restrict__ atts, const float* __restrict__ attd, int N)
{
    __shared__ float Ws[IN_F * HC1];   // 32KB
    __shared__ float s_as[HC1], s_ad[HC1];
    for (int i = threadIdx.x; i < IN_F * HC1; i += 256) Ws[i] = W1[i];
    if (threadIdx.x < HC1) { s_as[threadIdx.x] = atts[threadIdx.x]; s_ad[threadIdx.x] = attd[threadIdx.x]; }
    __syncthreads();

    const int jq = threadIdx.x & 3;
    const int j0 = jq * 16;
    const int pr = threadIdx.x >> 2;
    const long long n0 = (long long)blockIdx.x * 128 + pr * 2;
    const long long n1 = n0 + 1;
    const bool v0 = n0 < N, v1 = n1 < N;

    const float4* xp0 = (const float4*)(x + (v0 ? n0 : 0) * IN_F);
    const float4* xp1 = (const float4*)(x + (v1 ? n1 : 0) * IN_F);

    float acc0[16], acc1[16];
#pragma unroll
    for (int i = 0; i < 16; i++) { acc0[i] = 0.f; acc1[i] = 0.f; }

#pragma unroll 8
    for (int k4 = 0; k4 < IN_F / 4; k4++) {
        float4 xa = xp0[k4];
        float4 xb = xp1[k4];
        const float* wrow = &Ws[k4 * 4 * HC1 + j0];
#pragma unroll
        for (int kk = 0; kk < 4; kk++) {
            float xav = (&xa.x)[kk];
            float xbv = (&xb.x)[kk];
#pragma unroll
            for (int jj = 0; jj < 4; jj++) {
                float4 w = *(const float4*)(wrow + kk * HC1 + jj * 4);
                acc0[jj*4+0] += xav * w.x; acc0[jj*4+1] += xav * w.y;
                acc0[jj*4+2] += xav * w.z; acc0[jj*4+3] += xav * w.w;
                acc1[jj*4+0] += xbv * w.x; acc1[jj*4+1] += xbv * w.y;
                acc1[jj*4+2] += xbv * w.z; acc1[jj*4+3] += xbv * w.w;
            }
        }
    }

    const int h0 = j0 >> 3;
#pragma unroll
    for (int sel = 0; sel < 2; sel++) {
        const bool valid = sel ? v1 : v0;
        if (!valid) continue;
        const long long n = sel ? n1 : n0;
        float* acc = sel ? acc1 : acc0;

        float as0 = 0.f, ad0 = 0.f, as1 = 0.f, ad1 = 0.f;
#pragma unroll
        for (int c = 0; c < 8; c++) {
            as0 += acc[c]     * s_as[h0 * 8 + c];
            ad0 += acc[c]     * s_ad[h0 * 8 + c];
            as1 += acc[8 + c] * s_as[(h0 + 1) * 8 + c];
            ad1 += acc[8 + c] * s_ad[(h0 + 1) * 8 + c];
        }
        g_asrc1[n * H1 + h0]     = as0;  g_asrc1[n * H1 + h0 + 1] = as1;
        g_adst1[n * H1 + h0]     = ad0;  g_adst1[n * H1 + h0 + 1] = ad1;

        float4* hp = &g_h1[n * 16 + jq * 4];
#pragma unroll
        for (int q = 0; q < 4; q++)
            hp[q] = make_float4(acc[q*4+0], acc[q*4+1], acc[q*4+2], acc[q*4+3]);
    }
}

// ---------------------------------------------------------------------------
// KL1: fused layer-1 aggregate (gather, register acc, 2x-unrolled loop) +
//      normalize + ELU + h2@W2 + layer-2 attention. 8 lanes/node, 32 nodes/blk.
// ---------------------------------------------------------------------------
__global__ __launch_bounds__(256) void kL1_gather(
    const float* __restrict__ W2, const float* __restrict__ b1,
    const float* __restrict__ atts2, const float* __restrict__ attd2, int N)
{
    __shared__ float W2s[HC1 * OUT2];   // 10.2KB
    __shared__ float b1s[HC1], as2s[OUT2], ad2s[OUT2];
    for (int i = threadIdx.x; i < HC1 * OUT2; i += 256) W2s[i] = W2[i];
    if (threadIdx.x < HC1) b1s[threadIdx.x] = b1[threadIdx.x];
    if (threadIdx.x < OUT2) { as2s[threadIdx.x] = atts2[threadIdx.x]; ad2s[threadIdx.x] = attd2[threadIdx.x]; }
    __syncthreads();

    const int r = threadIdx.x & 7;
    const int n = blockIdx.x * 32 + (threadIdx.x >> 3);
    const int nc = (n < N) ? n : 0;

    const float adst = g_adst1[nc * H1 + r];
    const int beg = g_rowptr[nc];
    const int end = beg + g_deg[nc];

    // self-loop
    float w = __expf(lrelu(g_asrc1[nc * H1 + r] + adst));
    float denom = w;
    float4 a0 = g_h1[(long long)nc * 16 + r * 2];
    float4 a1 = g_h1[(long long)nc * 16 + r * 2 + 1];
    float acc[8] = { w*a0.x, w*a0.y, w*a0.z, w*a0.w, w*a1.x, w*a1.y, w*a1.z, w*a1.w };

    int p = beg;
    // 2x-unrolled main loop: both edges' gathers issue before either compute.
    for (; p + 2 <= end; p += 2) {
        int sa = g_esrc[p];
        int sb = g_esrc[p + 1];
        float ea = g_asrc1[sa * H1 + r];
        float eb = g_asrc1[sb * H1 + r];
        float4 va0 = g_h1[(long long)sa * 16 + r * 2];
        float4 va1 = g_h1[(long long)sa * 16 + r * 2 + 1];
        float4 vb0 = g_h1[(long long)sb * 16 + r * 2];
        float4 vb1 = g_h1[(long long)sb * 16 + r * 2 + 1];
        float wa = __expf(lrelu(ea + adst));
        float wb = __expf(lrelu(eb + adst));
        denom += wa + wb;
        acc[0] += wa * va0.x + wb * vb0.x; acc[1] += wa * va0.y + wb * vb0.y;
        acc[2] += wa * va0.z + wb * vb0.z; acc[3] += wa * va0.w + wb * vb0.w;
        acc[4] += wa * va1.x + wb * vb1.x; acc[5] += wa * va1.y + wb * vb1.y;
        acc[6] += wa * va1.z + wb * vb1.z; acc[7] += wa * va1.w + wb * vb1.w;
    }
    if (p < end) {
        int src = g_esrc[p];
        float wi = __expf(lrelu(g_asrc1[src * H1 + r] + adst));
        denom += wi;
        float4 v0 = g_h1[(long long)src * 16 + r * 2];
        float4 v1 = g_h1[(long long)src * 16 + r * 2 + 1];
        acc[0] += wi * v0.x; acc[1] += wi * v0.y; acc[2] += wi * v0.z; acc[3] += wi * v0.w;
        acc[4] += wi * v1.x; acc[5] += wi * v1.y; acc[6] += wi * v1.z; acc[7] += wi * v1.w;
    }

    // h2 = elu(acc/denom + b1)
    float inv = 1.0f / denom;
    float h2r[8];
    {
        const float* bb = &b1s[r * 8];
#pragma unroll
        for (int c = 0; c < 8; c++) {
            float v = acc[c] * inv + bb[c];
            h2r[c] = v > 0.f ? v : expm1f(v);
        }
    }

    // g = h2 @ W2 (width-8 shuffle GEMM); lane r owns cols r, r+8, ..., r+32
    float acc2[5] = {0.f, 0.f, 0.f, 0.f, 0.f};
#pragma unroll
    for (int k = 0; k < HC1; k++) {
        float hk = __shfl_sync(0xffffffffu, h2r[k & 7], k >> 3, 8);
#pragma unroll
        for (int i = 0; i < 5; i++) acc2[i] += hk * W2s[k * OUT2 + r + 8 * i];
    }

    float as = 0.f, ad = 0.f;
#pragma unroll
    for (int i = 0; i < 5; i++) { as += acc2[i] * as2s[r + 8 * i]; ad += acc2[i] * ad2s[r + 8 * i]; }
#pragma unroll
    for (int o = 4; o; o >>= 1) {
        as += __shfl_xor_sync(0xffffffffu, as, o, 8);
        ad += __shfl_xor_sync(0xffffffffu, ad, o, 8);
    }

    if (n < N) {
        if (r == 0) { g_asrc2[n] = as; g_adst2[n] = ad; }
        float* gp = g_g2 + (long long)n * OUT2;
#pragma unroll
        for (int i = 0; i < 5; i++) gp[r + 8 * i] = acc2[i];
    }
}

// ---------------------------------------------------------------------------
// KL2: fused layer-2 aggregate (gather, 2x-unrolled) + normalize + bias +
//      log_softmax. 16 lanes/node; lanes 0..9 each own one float4.
// ---------------------------------------------------------------------------
__global__ __launch_bounds__(256) void kL2_gather(
    const float* __restrict__ b2, float* __restrict__ out, int N)
{
    const int r = threadIdx.x & 15;
    const int n = blockIdx.x * 16 + (threadIdx.x >> 4);
    const int nc = (n < N) ? n : 0;
    const bool act = (r < 10);

    const float adst = g_adst2[nc];
    const int beg = g_rowptr[nc];
    const int end = beg + g_deg[nc];

    // self-loop
    float w = __expf(lrelu(g_asrc2[nc] + adst));
    float denom = w;
    float4 acc = make_float4(0.f, 0.f, 0.f, 0.f);
    if (act) {
        float4 g = ((const float4*)(g_g2 + (long long)nc * OUT2))[r];
        acc = make_float4(w * g.x, w * g.y, w * g.z, w * g.w);
    }

    int p = beg;
    for (; p + 2 <= end; p += 2) {
        int sa = g_esrc[p];
        int sb = g_esrc[p + 1];
        float ea = g_asrc2[sa];
        float eb = g_asrc2[sb];
        float4 ga = make_float4(0.f,0.f,0.f,0.f), gb = make_float4(0.f,0.f,0.f,0.f);
        if (act) {
            ga = ((const float4*)(g_g2 + (long long)sa * OUT2))[r];
            gb = ((const float4*)(g_g2 + (long long)sb * OUT2))[r];
        }
        float wa = __expf(lrelu(ea + adst));
        float wb = __expf(lrelu(eb + adst));
        denom += wa + wb;
        if (act) {
            acc.x += wa * ga.x + wb * gb.x; acc.y += wa * ga.y + wb * gb.y;
            acc.z += wa * ga.z + wb * gb.z; acc.w += wa * ga.w + wb * gb.w;
        }
    }
    if (p < end) {
        int src = g_esrc[p];
        float wi = __expf(lrelu(g_asrc2[src] + adst));
        denom += wi;
        if (act) {
            float4 g = ((const float4*)(g_g2 + (long long)src * OUT2))[r];
            acc.x += wi * g.x; acc.y += wi * g.y; acc.z += wi * g.z; acc.w += wi * g.w;
        }
    }

    float inv = 1.0f / denom;
    float4 v = make_float4(-3.0e38f, -3.0e38f, -3.0e38f, -3.0e38f);
    if (act) {
        float4 bb = ((const float4*)b2)[r];
        v = make_float4(acc.x * inv + bb.x, acc.y * inv + bb.y,
                        acc.z * inv + bb.z, acc.w * inv + bb.w);
    }

    // log_softmax across the 10 active lanes (width-16 reductions)
    float m = fmaxf(fmaxf(v.x, v.y), fmaxf(v.z, v.w));
#pragma unroll
    for (int o = 8; o; o >>= 1) m = fmaxf(m, __shfl_xor_sync(0xffffffffu, m, o, 16));
    float s = 0.f;
    if (act) s = expf(v.x - m) + expf(v.y - m) + expf(v.z - m) + expf(v.w - m);
#pragma unroll
    for (int o = 8; o; o >>= 1) s += __shfl_xor_sync(0xffffffffu, s, o, 16);
    float lse = m + logf(s);

    if (act && n < N) {
        float4 o4 = make_float4(v.x - lse, v.y - lse, v.z - lse, v.w - lse);
        ((float4*)(out + (long long)n * OUT2))[r] = o4;
    }
}

// ---------------------------------------------------------------------------
extern "C" void kernel_launch(void* const* d_in, const int* in_sizes, int n_in,
                              void* d_out, int out_size)
{
    const float* x     = (const float*)d_in[0];
    const void*  ei    = d_in[1];
    const float* W1    = (const float*)d_in[2];
    const float* atts1 = (const float*)d_in[3];
    const float* attd1 = (const float*)d_in[4];
    const float* b1    = (const float*)d_in[5];
    const float* W2    = (const float*)d_in[6];
    const float* atts2 = (const float*)d_in[7];
    const float* attd2 = (const float*)d_in[8];
    const float* b2    = (const float*)d_in[9];

    int N = in_sizes[0] / IN_F;
    int E = in_sizes[1] / 2;
    if (N > N_CAP) N = N_CAP;
    if (E > E_CAP) E = E_CAP;
    const int nb_scan = (N + 511) / 512;

    k0_detect<<<1, 256>>>((const unsigned int*)ei, 2 * E);
    k_zero<<<(N + 255) / 256, 256>>>(N);
    k_hist<<<(E + 255) / 256, 256>>>(ei, E);
    k_scan1<<<nb_scan, 512>>>(N);
    k_scan2<<<1, 256>>>(nb_scan);
    k_scan3<<<(N + 255) / 256, 256>>>(N);
    k_scatter<<<(E + 255) / 256, 256>>>(ei, E);

    k1_gemm_attn<<<(N + 127) / 128, 256>>>(x, W1, atts1, attd1, N);
    kL1_gather<<<(N + 31) / 32, 256>>>(W2, b1, atts2, attd2, N);
    kL2_gather<<<(N + 15) / 16, 256>>>(b2, (float*)d_out, N);
}

// round 11
// speedup vs baseline: 1.5161x; 1.0472x over previous
#include <cuda_runtime.h>
#include <cuda_fp16.h>
#include <cuda_bf16.h>

// ---------------------------------------------------------------------------
// GATnet 2-layer GAT, N=100000, E=1600000, IN=128, L1: 8x8 concat, ELU,
// L2: 1x40, log_softmax.
// R11: fp16 storage for gathered payloads (h1, g2) halves edge-pass L2 bytes;
// f32x2 packed FMA in k1; SAFE multi-kernel CSR build (no grid barrier).
// ---------------------------------------------------------------------------

#define N_CAP 100000
#define E_CAP 1600000
#define IN_F  128
#define HC1   64
#define H1    8
#define OUT2  40
#define NEG_SLOPE 0.2f

// Scratch (static device globals)
__device__ __align__(16) __half2 g_h1h[N_CAP * 32];   // [N][64] as half2 (128B/node)
__device__ float  g_asrc1[N_CAP * H1];
__device__ float  g_adst1[N_CAP * H1];
__device__ __align__(16) __half2 g_g2h[N_CAP * 20];   // [N][40] as half2 (80B/node)
__device__ float  g_asrc2[N_CAP];
__device__ float  g_adst2[N_CAP];
__device__ int    g_esrc[E_CAP];
__device__ int    g_deg[N_CAP];
__device__ int    g_rowptr[N_CAP];
__device__ int    g_cursor[N_CAP];
__device__ int    g_blksum[256];
__device__ int    g_is64;

__device__ __forceinline__ float lrelu(float v) { return v > 0.f ? v : NEG_SLOPE * v; }

__device__ __forceinline__ float2 h2f(unsigned int u) {
    __half2 h = *reinterpret_cast<__half2*>(&u);
    return __half22float2(h);
}

__device__ __forceinline__ unsigned long long pk2(float lo, float hi) {
    unsigned long long r;
    asm("mov.b64 %0, {%1, %2};" : "=l"(r) : "f"(lo), "f"(hi));
    return r;
}
__device__ __forceinline__ void unpk2(float& lo, float& hi, unsigned long long v) {
    asm("mov.b64 {%0, %1}, %2;" : "=f"(lo), "=f"(hi) : "l"(v));
}
__device__ __forceinline__ unsigned long long ffma2(
    unsigned long long a, unsigned long long b, unsigned long long c) {
    unsigned long long d;
    asm("fma.rn.f32x2 %0, %1, %2, %3;" : "=l"(d) : "l"(a), "l"(b), "l"(c));
    return d;
}

// ---------------------------------------------------------------------------
// K0: edge-index dtype detect (int64 stored little-endian => odd words all 0)
// ---------------------------------------------------------------------------
__global__ void k0_detect(const unsigned int* ei32, int nwords) {
    __shared__ int any_nz;
    if (threadIdx.x == 0) any_nz = 0;
    __syncthreads();
    int samples = 2048;
    if (samples * 2 > nwords) samples = nwords / 2;
    for (int i = threadIdx.x; i < samples; i += 256)
        if (ei32[2 * i + 1] != 0u) any_nz = 1;
    __syncthreads();
    if (threadIdx.x == 0) g_is64 = (any_nz == 0) ? 1 : 0;
}

// ---------------------------------------------------------------------------
// CSR construction (multi-kernel, no grid barrier — proven safe)
// ---------------------------------------------------------------------------
__global__ __launch_bounds__(256) void k_zero(int N) {
    int i = blockIdx.x * 256 + threadIdx.x;
    if (i < N) g_deg[i] = 0;
}

__global__ __launch_bounds__(256) void k_hist(const void* ei, int E) {
    int i = blockIdx.x * 256 + threadIdx.x;
    if (i >= E) return;
    int dst = g_is64 ? (int)((const long long*)ei)[E + i] : ((const int*)ei)[E + i];
    atomicAdd(&g_deg[dst], 1);
}

// shuffle-based inclusive scan over 512 elements per block
__global__ __launch_bounds__(512) void k_scan1(int N) {
    __shared__ int wsum[16];
    int i = blockIdx.x * 512 + threadIdx.x;
    int v = (i < N) ? g_deg[i] : 0;
    int lane = threadIdx.x & 31, warp = threadIdx.x >> 5;
    int x = v;
#pragma unroll
    for (int o = 1; o < 32; o <<= 1) {
        int t = __shfl_up_sync(0xffffffffu, x, o);
        if (lane >= o) x += t;
    }
    if (lane == 31) wsum[warp] = x;
    __syncthreads();
    if (warp == 0) {
        int ws = (lane < 16) ? wsum[lane] : 0;
#pragma unroll
        for (int o = 1; o < 16; o <<= 1) {
            int t = __shfl_up_sync(0xffffffffu, ws, o);
            if (lane >= o) ws += t;
        }
        if (lane < 16) wsum[lane] = ws;
    }
    __syncthreads();
    int base = warp ? wsum[warp - 1] : 0;
    if (i < N) g_rowptr[i] = base + x - v;   // exclusive
    if (threadIdx.x == 511) g_blksum[blockIdx.x] = base + x;
}

// parallel exclusive scan over <=256 block sums
__global__ __launch_bounds__(256) void k_scan2(int nb) {
    __shared__ int wsum[8];
    int lane = threadIdx.x & 31, warp = threadIdx.x >> 5;
    int v = (threadIdx.x < nb) ? g_blksum[threadIdx.x] : 0;
    int x = v;
#pragma unroll
    for (int o = 1; o < 32; o <<= 1) {
        int t = __shfl_up_sync(0xffffffffu, x, o);
        if (lane >= o) x += t;
    }
    if (lane == 31) wsum[warp] = x;
    __syncthreads();
    if (warp == 0) {
        int ws = (lane < 8) ? wsum[lane] : 0;
#pragma unroll
        for (int o = 1; o < 8; o <<= 1) {
            int t = __shfl_up_sync(0xffffffffu, ws, o);
            if (lane >= o) ws += t;
        }
        if (lane < 8) wsum[lane] = ws;
    }
    __syncthreads();
    int base = warp ? wsum[warp - 1] : 0;
    if (threadIdx.x < nb) g_blksum[threadIdx.x] = base + x - v;   // exclusive
}

__global__ __launch_bounds__(256) void k_scan3(int N) {
    int i = blockIdx.x * 256 + threadIdx.x;
    if (i >= N) return;
    int r = g_rowptr[i] + g_blksum[i >> 9];
    g_rowptr[i] = r;
    g_cursor[i] = r;
}

__global__ __launch_bounds__(256) void k_scatter(const void* ei, int E) {
    int i = blockIdx.x * 256 + threadIdx.x;
    if (i >= E) return;
    int src, dst;
    if (g_is64) {
        src = (int)((const long long*)ei)[i];
        dst = (int)((const long long*)ei)[E + i];
    } else {
        src = ((const int*)ei)[i];
        dst = ((const int*)ei)[E + i];
    }
    int pos = atomicAdd(&g_cursor[dst], 1);
    g_esrc[pos] = src;
}

// ---------------------------------------------------------------------------
// K1: h1 = x @ W1 (f32x2 packed FMA); a_src1/a_dst1 = h1 . att; store h1 fp16.
// Block: 256 thr -> 128 nodes x 64 outs. Thread: 2 nodes x 16 outs (8 pairs).
// ---------------------------------------------------------------------------
__global__ __launch_bounds__(256) void k1_gemm_attn(
    const float* __restrict__ x, const float* __restrict__ W1,
    const float* __restrict__ atts, const float* __restrict__ attd, int N)
{
    __shared__ __align__(16) float Ws[IN_F * HC1];   // 32KB
    __shared__ float s_as[HC1], s_ad[HC1];
    for (int i = threadIdx.x; i < IN_F * HC1; i += 256) Ws[i] = W1[i];
    if (threadIdx.x < HC1) { s_as[threadIdx.x] = atts[threadIdx.x]; s_ad[threadIdx.x] = attd[threadIdx.x]; }
    __syncthreads();

    const int jq = threadIdx.x & 3;
    const int j0 = jq * 16;
    const int pr = threadIdx.x >> 2;
    const int n0 = blockIdx.x * 128 + pr * 2;
    const int n1 = n0 + 1;
    const bool v0 = n0 < N, v1 = n1 < N;

    const float4* xp0 = (const float4*)(x + (long long)(v0 ? n0 : 0) * IN_F);
    const float4* xp1 = (const float4*)(x + (long long)(v1 ? n1 : 0) * IN_F);

    unsigned long long a0p[8], a1p[8];
    const unsigned long long Z = pk2(0.f, 0.f);
#pragma unroll
    for (int i = 0; i < 8; i++) { a0p[i] = Z; a1p[i] = Z; }

#pragma unroll 8
    for (int k4 = 0; k4 < IN_F / 4; k4++) {
        float4 xa = xp0[k4];
        float4 xb = xp1[k4];
        const float* wrow = &Ws[k4 * 4 * HC1 + j0];
#pragma unroll
        for (int kk = 0; kk < 4; kk++) {
            float xav = (&xa.x)[kk];
            float xbv = (&xb.x)[kk];
            unsigned long long xap = pk2(xav, xav);
            unsigned long long xbp = pk2(xbv, xbv);
#pragma unroll
            for (int jj = 0; jj < 4; jj++) {
                ulonglong2 w2 = *(const ulonglong2*)(wrow + kk * HC1 + jj * 4);
                a0p[jj*2+0] = ffma2(xap, w2.x, a0p[jj*2+0]);
                a0p[jj*2+1] = ffma2(xap, w2.y, a0p[jj*2+1]);
                a1p[jj*2+0] = ffma2(xbp, w2.x, a1p[jj*2+0]);
                a1p[jj*2+1] = ffma2(xbp, w2.y, a1p[jj*2+1]);
            }
        }
    }

    const int h0 = j0 >> 3;
#pragma unroll
    for (int sel = 0; sel < 2; sel++) {
        const bool valid = sel ? v1 : v0;
        if (!valid) continue;
        const int n = sel ? n1 : n0;
        unsigned long long* ap = sel ? a1p : a0p;
        float acc[16];
#pragma unroll
        for (int i = 0; i < 8; i++) unpk2(acc[2*i], acc[2*i+1], ap[i]);

        float as0 = 0.f, ad0 = 0.f, as1 = 0.f, ad1 = 0.f;
#pragma unroll
        for (int c = 0; c < 8; c++) {
            as0 += acc[c]     * s_as[h0 * 8 + c];
            ad0 += acc[c]     * s_ad[h0 * 8 + c];
            as1 += acc[8 + c] * s_as[(h0 + 1) * 8 + c];
            ad1 += acc[8 + c] * s_ad[(h0 + 1) * 8 + c];
        }
        g_asrc1[n * H1 + h0]     = as0;  g_asrc1[n * H1 + h0 + 1] = as1;
        g_adst1[n * H1 + h0]     = ad0;  g_adst1[n * H1 + h0 + 1] = ad1;

        union { __half2 h[8]; uint4 u[2]; } cv;
#pragma unroll
        for (int q = 0; q < 8; q++) cv.h[q] = __floats2half2_rn(acc[2*q], acc[2*q+1]);
        uint4* hp = (uint4*)(g_h1h + n * 32 + jq * 8);
        hp[0] = cv.u[0];
        hp[1] = cv.u[1];
    }
}

// ---------------------------------------------------------------------------
// KL1: fused layer-1 aggregate (gather fp16 payload) + normalize + ELU +
//      h2@W2 + layer-2 attention. 8 lanes/node, 32 nodes/block.
// ---------------------------------------------------------------------------
__global__ __launch_bounds__(256) void kL1_gather(
    const float* __restrict__ W2, const float* __restrict__ b1,
    const float* __restrict__ atts2, const float* __restrict__ attd2, int N)
{
    __shared__ float W2s[HC1 * OUT2];   // 10.2KB
    __shared__ float b1s[HC1], as2s[OUT2], ad2s[OUT2];
    for (int i = threadIdx.x; i < HC1 * OUT2; i += 256) W2s[i] = W2[i];
    if (threadIdx.x < HC1) b1s[threadIdx.x] = b1[threadIdx.x];
    if (threadIdx.x < OUT2) { as2s[threadIdx.x] = atts2[threadIdx.x]; ad2s[threadIdx.x] = attd2[threadIdx.x]; }
    __syncthreads();

    const int r = threadIdx.x & 7;
    const int n = blockIdx.x * 32 + (threadIdx.x >> 3);
    const int nc = (n < N) ? n : 0;

    const float adst = g_adst1[nc * H1 + r];
    const int beg = g_rowptr[nc];
    const int end = beg + g_deg[nc];

    // self-loop
    float w = __expf(lrelu(g_asrc1[nc * H1 + r] + adst));
    float denom = w;
    float acc[8];
    {
        uint4 u = *(const uint4*)(g_h1h + nc * 32 + r * 4);
        float2 f0 = h2f(u.x), f1 = h2f(u.y), f2 = h2f(u.z), f3 = h2f(u.w);
        acc[0] = w * f0.x; acc[1] = w * f0.y; acc[2] = w * f1.x; acc[3] = w * f1.y;
        acc[4] = w * f2.x; acc[5] = w * f2.y; acc[6] = w * f3.x; acc[7] = w * f3.y;
    }

    int p = beg;
    for (; p + 2 <= end; p += 2) {
        int sa = g_esrc[p];
        int sb = g_esrc[p + 1];
        float ea = g_asrc1[sa * H1 + r];
        float eb = g_asrc1[sb * H1 + r];
        uint4 ua = *(const uint4*)(g_h1h + sa * 32 + r * 4);
        uint4 ub = *(const uint4*)(g_h1h + sb * 32 + r * 4);
        float wa = __expf(lrelu(ea + adst));
        float wb = __expf(lrelu(eb + adst));
        denom += wa + wb;
        float2 f;
        f = h2f(ua.x); acc[0] += wa * f.x; acc[1] += wa * f.y;
        f = h2f(ua.y); acc[2] += wa * f.x; acc[3] += wa * f.y;
        f = h2f(ua.z); acc[4] += wa * f.x; acc[5] += wa * f.y;
        f = h2f(ua.w); acc[6] += wa * f.x; acc[7] += wa * f.y;
        f = h2f(ub.x); acc[0] += wb * f.x; acc[1] += wb * f.y;
        f = h2f(ub.y); acc[2] += wb * f.x; acc[3] += wb * f.y;
        f = h2f(ub.z); acc[4] += wb * f.x; acc[5] += wb * f.y;
        f = h2f(ub.w); acc[6] += wb * f.x; acc[7] += wb * f.y;
    }
    if (p < end) {
        int src = g_esrc[p];
        float wi = __expf(lrelu(g_asrc1[src * H1 + r] + adst));
        denom += wi;
        uint4 u = *(const uint4*)(g_h1h + src * 32 + r * 4);
        float2 f;
        f = h2f(u.x); acc[0] += wi * f.x; acc[1] += wi * f.y;
        f = h2f(u.y); acc[2] += wi * f.x; acc[3] += wi * f.y;
        f = h2f(u.z); acc[4] += wi * f.x; acc[5] += wi * f.y;
        f = h2f(u.w); acc[6] += wi * f.x; acc[7] += wi * f.y;
    }

    // h2 = elu(acc/denom + b1)
    float inv = 1.0f / denom;
    float h2r[8];
    {
        const float* bb = &b1s[r * 8];
#pragma unroll
        for (int c = 0; c < 8; c++) {
            float v = acc[c] * inv + bb[c];
            h2r[c] = v > 0.f ? v : expm1f(v);
        }
    }

    // g = h2 @ W2 (width-8 shuffle GEMM); lane r owns cols r, r+8, ..., r+32
    float acc2[5] = {0.f, 0.f, 0.f, 0.f, 0.f};
#pragma unroll
    for (int k = 0; k < HC1; k++) {
        float hk = __shfl_sync(0xffffffffu, h2r[k & 7], k >> 3, 8);
#pragma unroll
        for (int i = 0; i < 5; i++) acc2[i] += hk * W2s[k * OUT2 + r + 8 * i];
    }

    float as = 0.f, ad = 0.f;
#pragma unroll
    for (int i = 0; i < 5; i++) { as += acc2[i] * as2s[r + 8 * i]; ad += acc2[i] * ad2s[r + 8 * i]; }
#pragma unroll
    for (int o = 4; o; o >>= 1) {
        as += __shfl_xor_sync(0xffffffffu, as, o, 8);
        ad += __shfl_xor_sync(0xffffffffu, ad, o, 8);
    }

    // pack g2 to half2: even lane r supplies lo (col r+8i), lane r+1 the hi
    float hi_[5];
#pragma unroll
    for (int i = 0; i < 5; i++) hi_[i] = __shfl_xor_sync(0xffffffffu, acc2[i], 1, 8);

    if (n < N) {
        if (r == 0) { g_asrc2[n] = as; g_adst2[n] = ad; }
        if ((r & 1) == 0) {
            __half2* gp = g_g2h + n * 20;
#pragma unroll
            for (int i = 0; i < 5; i++)
                gp[(r >> 1) + 4 * i] = __floats2half2_rn(acc2[i], hi_[i]);
        }
    }
}

// ---------------------------------------------------------------------------
// KL2: fused layer-2 aggregate (gather fp16 payload) + normalize + bias +
//      log_softmax. 16 lanes/node; lanes 0..9 own 4 channels (4r..4r+3).
// ---------------------------------------------------------------------------
__global__ __launch_bounds__(256) void kL2_gather(
    const float* __restrict__ b2, float* __restrict__ out, int N)
{
    const int r = threadIdx.x & 15;
    const int n = blockIdx.x * 16 + (threadIdx.x >> 4);
    const int nc = (n < N) ? n : 0;
    const bool act = (r < 10);

    const float adst = g_adst2[nc];
    const int beg = g_rowptr[nc];
    const int end = beg + g_deg[nc];

    // self-loop
    float w = __expf(lrelu(g_asrc2[nc] + adst));
    float denom = w;
    float4 acc = make_float4(0.f, 0.f, 0.f, 0.f);
    if (act) {
        uint2 u = *(const uint2*)(g_g2h + nc * 20 + r * 2);
        float2 fa = h2f(u.x), fb = h2f(u.y);
        acc = make_float4(w * fa.x, w * fa.y, w * fb.x, w * fb.y);
    }

    int p = beg;
    for (; p + 2 <= end; p += 2) {
        int sa = g_esrc[p];
        int sb = g_esrc[p + 1];
        float ea = g_asrc2[sa];
        float eb = g_asrc2[sb];
        uint2 ua = make_uint2(0u, 0u), ub = make_uint2(0u, 0u);
        if (act) {
            ua = *(const uint2*)(g_g2h + sa * 20 + r * 2);
            ub = *(const uint2*)(g_g2h + sb * 20 + r * 2);
        }
        float wa = __expf(lrelu(ea + adst));
        float wb = __expf(lrelu(eb + adst));
        denom += wa + wb;
        if (act) {
            float2 f;
            f = h2f(ua.x); acc.x += wa * f.x; acc.y += wa * f.y;
            f = h2f(ua.y); acc.z += wa * f.x; acc.w += wa * f.y;
            f = h2f(ub.x); acc.x += wb * f.x; acc.y += wb * f.y;
            f = h2f(ub.y); acc.z += wb * f.x; acc.w += wb * f.y;
        }
    }
    if (p < end) {
        int src = g_esrc[p];
        float wi = __expf(lrelu(g_asrc2[src] + adst));
        denom += wi;
        if (act) {
            uint2 u = *(const uint2*)(g_g2h + src * 20 + r * 2);
            float2 fa = h2f(u.x), fb = h2f(u.y);
            acc.x += wi * fa.x; acc.y += wi * fa.y; acc.z += wi * fb.x; acc.w += wi * fb.y;
        }
    }

    float inv = 1.0f / denom;
    float4 v = make_float4(-3.0e38f, -3.0e38f, -3.0e38f, -3.0e38f);
    if (act) {
        float4 bb = ((const float4*)b2)[r];
        v = make_float4(acc.x * inv + bb.x, acc.y * inv + bb.y,
                        acc.z * inv + bb.z, acc.w * inv + bb.w);
    }

    // log_softmax across the 10 active lanes (width-16 reductions)
    float m = fmaxf(fmaxf(v.x, v.y), fmaxf(v.z, v.w));
#pragma unroll
    for (int o = 8; o; o >>= 1) m = fmaxf(m, __shfl_xor_sync(0xffffffffu, m, o, 16));
    float s = 0.f;
    if (act) s = expf(v.x - m) + expf(v.y - m) + expf(v.z - m) + expf(v.w - m);
#pragma unroll
    for (int o = 8; o; o >>= 1) s += __shfl_xor_sync(0xffffffffu, s, o, 16);
    float lse = m + logf(s);

    if (act && n < N) {
        float4 o4 = make_float4(v.x - lse, v.y - lse, v.z - lse, v.w - lse);
        ((float4*)(out + (long long)n * OUT2))[r] = o4;
    }
}

// ---------------------------------------------------------------------------
extern "C" void kernel_launch(void* const* d_in, const int* in_sizes, int n_in,
                              void* d_out, int out_size)
{
    const float* x     = (const float*)d_in[0];
    const void*  ei    = d_in[1];
    const float* W1    = (const float*)d_in[2];
    const float* atts1 = (const float*)d_in[3];
    const float* attd1 = (const float*)d_in[4];
    const float* b1    = (const float*)d_in[5];
    const float* W2    = (const float*)d_in[6];
    const float* atts2 = (const float*)d_in[7];
    const float* attd2 = (const float*)d_in[8];
    const float* b2    = (const float*)d_in[9];

    int N = in_sizes[0] / IN_F;
    int E = in_sizes[1] / 2;
    if (N > N_CAP) N = N_CAP;
    if (E > E_CAP) E = E_CAP;
    const int nb_scan = (N + 511) / 512;

    k0_detect<<<1, 256>>>((const unsigned int*)ei, 2 * E);
    k_zero<<<(N + 255) / 256, 256>>>(N);
    k_hist<<<(E + 255) / 256, 256>>>(ei, E);
    k_scan1<<<nb_scan, 512>>>(N);
    k_scan2<<<1, 256>>>(nb_scan);
    k_scan3<<<(N + 255) / 256, 256>>>(N);
    k_scatter<<<(E + 255) / 256, 256>>>(ei, E);

    k1_gemm_attn<<<(N + 127) / 128, 256>>>(x, W1, atts1, attd1, N);
    kL1_gather<<<(N + 31) / 32, 256>>>(W2, b1, atts2, attd2, N);
    kL2_gather<<<(N + 15) / 16, 256>>>(b2, (float*)d_out, N);
}

// round 13
// speedup vs baseline: 1.5163x; 1.0001x over previous
#include <cuda_runtime.h>
#include <cuda_fp16.h>
#include <cuda_bf16.h>

// ---------------------------------------------------------------------------
// GATnet 2-layer GAT, N=100000, E=1600000, IN=128, L1: 8x8 concat, ELU,
// L2: 1x40, log_softmax.
// R13 (= R12 resubmit; R12 hit infra flake): edge softmax weights via
//   w = max(exp(as)exp(ad), exp(.2as)exp(.2ad))
// (exact rewrite of exp(lrelu(as+ad)) by monotonicity of exp) -> ZERO MUFU in
// edge loops (binding pipe: 38.4M EX2 ~ 273us floor matched R11's 274.5us).
// exp factors precomputed in k1/kL1 epilogues. fp16 payloads + f32x2 k1 kept.
// ---------------------------------------------------------------------------

#define N_CAP 100000
#define E_CAP 1600000
#define IN_F  128
#define HC1   64
#define H1    8
#define OUT2  40
#define NEG_SLOPE 0.2f

// Scratch (static device globals)
__device__ __align__(16) __half2 g_h1h[N_CAP * 32];   // [N][64] as half2 (128B/node)
__device__ float2 g_e1s[N_CAP * H1];   // (exp(as), exp(.2 as)) layer 1
__device__ float2 g_e1d[N_CAP * H1];   // (exp(ad), exp(.2 ad)) layer 1
__device__ __align__(16) __half2 g_g2h[N_CAP * 20];   // [N][40] as half2 (80B/node)
__device__ float2 g_e2s[N_CAP];        // layer 2 src factors
__device__ float2 g_e2d[N_CAP];        // layer 2 dst factors
__device__ int    g_esrc[E_CAP];
__device__ int    g_deg[N_CAP];
__device__ int    g_rowptr[N_CAP];
__device__ int    g_cursor[N_CAP];
__device__ int    g_blksum[256];
__device__ int    g_is64;

__device__ __forceinline__ float2 h2f(unsigned int u) {
    __half2 h = *reinterpret_cast<__half2*>(&u);
    return __half22float2(h);
}

__device__ __forceinline__ unsigned long long pk2(float lo, float hi) {
    unsigned long long r;
    asm("mov.b64 %0, {%1, %2};" : "=l"(r) : "f"(lo), "f"(hi));
    return r;
}
__device__ __forceinline__ void unpk2(float& lo, float& hi, unsigned long long v) {
    asm("mov.b64 {%0, %1}, %2;" : "=f"(lo), "=f"(hi) : "l"(v));
}
__device__ __forceinline__ unsigned long long ffma2(
    unsigned long long a, unsigned long long b, unsigned long long c) {
    unsigned long long d;
    asm("fma.rn.f32x2 %0, %1, %2, %3;" : "=l"(d) : "l"(a), "l"(b), "l"(c));
    return d;
}

// w = exp(lrelu(a_s + a_d)) = max(exp(as)exp(ad), exp(.2as)exp(.2ad))
__device__ __forceinline__ float wmax(float2 s, float2 d) {
    return fmaxf(s.x * d.x, s.y * d.y);
}

// ---------------------------------------------------------------------------
// K0: edge-index dtype detect (int64 stored little-endian => odd words all 0)
// ---------------------------------------------------------------------------
__global__ void k0_detect(const unsigned int* ei32, int nwords) {
    __shared__ int any_nz;
    if (threadIdx.x == 0) any_nz = 0;
    __syncthreads();
    int samples = 2048;
    if (samples * 2 > nwords) samples = nwords / 2;
    for (int i = threadIdx.x; i < samples; i += 256)
        if (ei32[2 * i + 1] != 0u) any_nz = 1;
    __syncthreads();
    if (threadIdx.x == 0) g_is64 = (any_nz == 0) ? 1 : 0;
}

// ---------------------------------------------------------------------------
// CSR construction (multi-kernel, no grid barrier — proven safe)
// ---------------------------------------------------------------------------
__global__ __launch_bounds__(256) void k_zero(int N) {
    int i = blockIdx.x * 256 + threadIdx.x;
    if (i < N) g_deg[i] = 0;
}

__global__ __launch_bounds__(256) void k_hist(const void* ei, int E) {
    int i = blockIdx.x * 256 + threadIdx.x;
    if (i >= E) return;
    int dst = g_is64 ? (int)((const long long*)ei)[E + i] : ((const int*)ei)[E + i];
    atomicAdd(&g_deg[dst], 1);
}

__global__ __launch_bounds__(512) void k_scan1(int N) {
    __shared__ int wsum[16];
    int i = blockIdx.x * 512 + threadIdx.x;
    int v = (i < N) ? g_deg[i] : 0;
    int lane = threadIdx.x & 31, warp = threadIdx.x >> 5;
    int x = v;
#pragma unroll
    for (int o = 1; o < 32; o <<= 1) {
        int t = __shfl_up_sync(0xffffffffu, x, o);
        if (lane >= o) x += t;
    }
    if (lane == 31) wsum[warp] = x;
    __syncthreads();
    if (warp == 0) {
        int ws = (lane < 16) ? wsum[lane] : 0;
#pragma unroll
        for (int o = 1; o < 16; o <<= 1) {
            int t = __shfl_up_sync(0xffffffffu, ws, o);
            if (lane >= o) ws += t;
        }
        if (lane < 16) wsum[lane] = ws;
    }
    __syncthreads();
    int base = warp ? wsum[warp - 1] : 0;
    if (i < N) g_rowptr[i] = base + x - v;   // exclusive
    if (threadIdx.x == 511) g_blksum[blockIdx.x] = base + x;
}

__global__ __launch_bounds__(256) void k_scan2(int nb) {
    __shared__ int wsum[8];
    int lane = threadIdx.x & 31, warp = threadIdx.x >> 5;
    int v = (threadIdx.x < nb) ? g_blksum[threadIdx.x] : 0;
    int x = v;
#pragma unroll
    for (int o = 1; o < 32; o <<= 1) {
        int t = __shfl_up_sync(0xffffffffu, x, o);
        if (lane >= o) x += t;
    }
    if (lane == 31) wsum[warp] = x;
    __syncthreads();
    if (warp == 0) {
        int ws = (lane < 8) ? wsum[lane] : 0;
#pragma unroll
        for (int o = 1; o < 8; o <<= 1) {
            int t = __shfl_up_sync(0xffffffffu, ws, o);
            if (lane >= o) ws += t;
        }
        if (lane < 8) wsum[lane] = ws;
    }
    __syncthreads();
    int base = warp ? wsum[warp - 1] : 0;
    if (threadIdx.x < nb) g_blksum[threadIdx.x] = base + x - v;   // exclusive
}

__global__ __launch_bounds__(256) void k_scan3(int N) {
    int i = blockIdx.x * 256 + threadIdx.x;
    if (i >= N) return;
    int r = g_rowptr[i] + g_blksum[i >> 9];
    g_rowptr[i] = r;
    g_cursor[i] = r;
}

__global__ __launch_bounds__(256) void k_scatter(const void* ei, int E) {
    int i = blockIdx.x * 256 + threadIdx.x;
    if (i >= E) return;
    int src, dst;
    if (g_is64) {
        src = (int)((const long long*)ei)[i];
        dst = (int)((const long long*)ei)[E + i];
    } else {
        src = ((const int*)ei)[i];
        dst = ((const int*)ei)[E + i];
    }
    int pos = atomicAdd(&g_cursor[dst], 1);
    g_esrc[pos] = src;
}

// ---------------------------------------------------------------------------
// K1: h1 = x @ W1 (f32x2 packed FMA); exp-factor pairs for layer-1 attention;
// store h1 fp16. 256 thr -> 128 nodes x 64 outs; thread: 2 nodes x 16 outs.
// ---------------------------------------------------------------------------
__global__ __launch_bounds__(256) void k1_gemm_attn(
    const float* __restrict__ x, const float* __restrict__ W1,
    const float* __restrict__ atts, const float* __restrict__ attd, int N)
{
    __shared__ __align__(16) float Ws[IN_F * HC1];   // 32KB
    __shared__ float s_as[HC1], s_ad[HC1];
    for (int i = threadIdx.x; i < IN_F * HC1; i += 256) Ws[i] = W1[i];
    if (threadIdx.x < HC1) { s_as[threadIdx.x] = atts[threadIdx.x]; s_ad[threadIdx.x] = attd[threadIdx.x]; }
    __syncthreads();

    const int jq = threadIdx.x & 3;
    const int j0 = jq * 16;
    const int pr = threadIdx.x >> 2;
    const int n0 = blockIdx.x * 128 + pr * 2;
    const int n1 = n0 + 1;
    const bool v0 = n0 < N, v1 = n1 < N;

    const float4* xp0 = (const float4*)(x + (long long)(v0 ? n0 : 0) * IN_F);
    const float4* xp1 = (const float4*)(x + (long long)(v1 ? n1 : 0) * IN_F);

    unsigned long long a0p[8], a1p[8];
    const unsigned long long Z = pk2(0.f, 0.f);
#pragma unroll
    for (int i = 0; i < 8; i++) { a0p[i] = Z; a1p[i] = Z; }

#pragma unroll 8
    for (int k4 = 0; k4 < IN_F / 4; k4++) {
        float4 xa = xp0[k4];
        float4 xb = xp1[k4];
        const float* wrow = &Ws[k4 * 4 * HC1 + j0];
#pragma unroll
        for (int kk = 0; kk < 4; kk++) {
            float xav = (&xa.x)[kk];
            float xbv = (&xb.x)[kk];
            unsigned long long xap = pk2(xav, xav);
            unsigned long long xbp = pk2(xbv, xbv);
#pragma unroll
            for (int jj = 0; jj < 4; jj++) {
                ulonglong2 w2 = *(const ulonglong2*)(wrow + kk * HC1 + jj * 4);
                a0p[jj*2+0] = ffma2(xap, w2.x, a0p[jj*2+0]);
                a0p[jj*2+1] = ffma2(xap, w2.y, a0p[jj*2+1]);
                a1p[jj*2+0] = ffma2(xbp, w2.x, a1p[jj*2+0]);
                a1p[jj*2+1] = ffma2(xbp, w2.y, a1p[jj*2+1]);
            }
        }
    }

    const int h0 = j0 >> 3;
#pragma unroll
    for (int sel = 0; sel < 2; sel++) {
        const bool valid = sel ? v1 : v0;
        if (!valid) continue;
        const int n = sel ? n1 : n0;
        unsigned long long* ap = sel ? a1p : a0p;
        float acc[16];
#pragma unroll
        for (int i = 0; i < 8; i++) unpk2(acc[2*i], acc[2*i+1], ap[i]);

        float as0 = 0.f, ad0 = 0.f, as1 = 0.f, ad1 = 0.f;
#pragma unroll
        for (int c = 0; c < 8; c++) {
            as0 += acc[c]     * s_as[h0 * 8 + c];
            ad0 += acc[c]     * s_ad[h0 * 8 + c];
            as1 += acc[8 + c] * s_as[(h0 + 1) * 8 + c];
            ad1 += acc[8 + c] * s_ad[(h0 + 1) * 8 + c];
        }
        g_e1s[n * H1 + h0]     = make_float2(__expf(as0), __expf(NEG_SLOPE * as0));
        g_e1s[n * H1 + h0 + 1] = make_float2(__expf(as1), __expf(NEG_SLOPE * as1));
        g_e1d[n * H1 + h0]     = make_float2(__expf(ad0), __expf(NEG_SLOPE * ad0));
        g_e1d[n * H1 + h0 + 1] = make_float2(__expf(ad1), __expf(NEG_SLOPE * ad1));

        union { __half2 h[8]; uint4 u[2]; } cv;
#pragma unroll
        for (int q = 0; q < 8; q++) cv.h[q] = __floats2half2_rn(acc[2*q], acc[2*q+1]);
        uint4* hp = (uint4*)(g_h1h + n * 32 + jq * 8);
        hp[0] = cv.u[0];
        hp[1] = cv.u[1];
    }
}

// ---------------------------------------------------------------------------
// KL1: fused layer-1 aggregate (exp-free weights, fp16 payload) + normalize +
//      ELU + h2@W2 + layer-2 exp factors. 8 lanes/node, 32 nodes/block.
// ---------------------------------------------------------------------------
__global__ __launch_bounds__(256) void kL1_gather(
    const float* __restrict__ W2, const float* __restrict__ b1,
    const float* __restrict__ atts2, const float* __restrict__ attd2, int N)
{
    __shared__ float W2s[HC1 * OUT2];   // 10.2KB
    __shared__ float b1s[HC1], as2s[OUT2], ad2s[OUT2];
    for (int i = threadIdx.x; i < HC1 * OUT2; i += 256) W2s[i] = W2[i];
    if (threadIdx.x < HC1) b1s[threadIdx.x] = b1[threadIdx.x];
    if (threadIdx.x < OUT2) { as2s[threadIdx.x] = atts2[threadIdx.x]; ad2s[threadIdx.x] = attd2[threadIdx.x]; }
    __syncthreads();

    const int r = threadIdx.x & 7;
    const int n = blockIdx.x * 32 + (threadIdx.x >> 3);
    const int nc = (n < N) ? n : 0;

    const float2 d12 = g_e1d[nc * H1 + r];   // dst factors, hoisted
    const int beg = g_rowptr[nc];
    const int end = beg + g_deg[nc];

    // self-loop
    float w = wmax(g_e1s[nc * H1 + r], d12);
    float denom = w;
    float acc[8];
    {
        uint4 u = *(const uint4*)(g_h1h + nc * 32 + r * 4);
        float2 f0 = h2f(u.x), f1 = h2f(u.y), f2 = h2f(u.z), f3 = h2f(u.w);
        acc[0] = w * f0.x; acc[1] = w * f0.y; acc[2] = w * f1.x; acc[3] = w * f1.y;
        acc[4] = w * f2.x; acc[5] = w * f2.y; acc[6] = w * f3.x; acc[7] = w * f3.y;
    }

    int p = beg;
    for (; p + 2 <= end; p += 2) {
        int sa = g_esrc[p];
        int sb = g_esrc[p + 1];
        float2 ea = g_e1s[sa * H1 + r];
        float2 eb = g_e1s[sb * H1 + r];
        uint4 ua = *(const uint4*)(g_h1h + sa * 32 + r * 4);
        uint4 ub = *(const uint4*)(g_h1h + sb * 32 + r * 4);
        float wa = wmax(ea, d12);
        float wb = wmax(eb, d12);
        denom += wa + wb;
        float2 f;
        f = h2f(ua.x); acc[0] += wa * f.x; acc[1] += wa * f.y;
        f = h2f(ua.y); acc[2] += wa * f.x; acc[3] += wa * f.y;
        f = h2f(ua.z); acc[4] += wa * f.x; acc[5] += wa * f.y;
        f = h2f(ua.w); acc[6] += wa * f.x; acc[7] += wa * f.y;
        f = h2f(ub.x); acc[0] += wb * f.x; acc[1] += wb * f.y;
        f = h2f(ub.y); acc[2] += wb * f.x; acc[3] += wb * f.y;
        f = h2f(ub.z); acc[4] += wb * f.x; acc[5] += wb * f.y;
        f = h2f(ub.w); acc[6] += wb * f.x; acc[7] += wb * f.y;
    }
    if (p < end) {
        int src = g_esrc[p];
        float wi = wmax(g_e1s[src * H1 + r], d12);
        denom += wi;
        uint4 u = *(const uint4*)(g_h1h + src * 32 + r * 4);
        float2 f;
        f = h2f(u.x); acc[0] += wi * f.x; acc[1] += wi * f.y;
        f = h2f(u.y); acc[2] += wi * f.x; acc[3] += wi * f.y;
        f = h2f(u.z); acc[4] += wi * f.x; acc[5] += wi * f.y;
        f = h2f(u.w); acc[6] += wi * f.x; acc[7] += wi * f.y;
    }

    // h2 = elu(acc/denom + b1)
    float inv = 1.0f / denom;
    float h2r[8];
    {
        const float* bb = &b1s[r * 8];
#pragma unroll
        for (int c = 0; c < 8; c++) {
            float v = acc[c] * inv + bb[c];
            h2r[c] = v > 0.f ? v : expm1f(v);
        }
    }

    // g = h2 @ W2 (width-8 shuffle GEMM); lane r owns cols r, r+8, ..., r+32
    float acc2[5] = {0.f, 0.f, 0.f, 0.f, 0.f};
#pragma unroll
    for (int k = 0; k < HC1; k++) {
        float hk = __shfl_sync(0xffffffffu, h2r[k & 7], k >> 3, 8);
#pragma unroll
        for (int i = 0; i < 5; i++) acc2[i] += hk * W2s[k * OUT2 + r + 8 * i];
    }

    float as = 0.f, ad = 0.f;
#pragma unroll
    for (int i = 0; i < 5; i++) { as += acc2[i] * as2s[r + 8 * i]; ad += acc2[i] * ad2s[r + 8 * i]; }
#pragma unroll
    for (int o = 4; o; o >>= 1) {
        as += __shfl_xor_sync(0xffffffffu, as, o, 8);
        ad += __shfl_xor_sync(0xffffffffu, ad, o, 8);
    }

    // pack g2 to half2: even lane r supplies lo (col r+8i), lane r+1 the hi
    float hi_[5];
#pragma unroll
    for (int i = 0; i < 5; i++) hi_[i] = __shfl_xor_sync(0xffffffffu, acc2[i], 1, 8);

    if (n < N) {
        if (r == 0) {
            g_e2s[n] = make_float2(__expf(as), __expf(NEG_SLOPE * as));
            g_e2d[n] = make_float2(__expf(ad), __expf(NEG_SLOPE * ad));
        }
        if ((r & 1) == 0) {
            __half2* gp = g_g2h + n * 20;
#pragma unroll
            for (int i = 0; i < 5; i++)
                gp[(r >> 1) + 4 * i] = __floats2half2_rn(acc2[i], hi_[i]);
        }
    }
}

// ---------------------------------------------------------------------------
// KL2: fused layer-2 aggregate (exp-free weights, fp16 payload) + normalize +
//      bias + log_softmax. 16 lanes/node; lanes 0..9 own 4 channels.
// ---------------------------------------------------------------------------
__global__ __launch_bounds__(256) void kL2_gather(
    const float* __restrict__ b2, float* __restrict__ out, int N)
{
    const int r = threadIdx.x & 15;
    const int n = blockIdx.x * 16 + (threadIdx.x >> 4);
    const int nc = (n < N) ? n : 0;
    const bool act = (r < 10);

    const float2 dd = g_e2d[nc];   // dst factors, hoisted
    const int beg = g_rowptr[nc];
    const int end = beg + g_deg[nc];

    // self-loop
    float w = wmax(g_e2s[nc], dd);
    float denom = w;
    float4 acc = make_float4(0.f, 0.f, 0.f, 0.f);
    if (act) {
        uint2 u = *(const uint2*)(g_g2h + nc * 20 + r * 2);
        float2 fa = h2f(u.x), fb = h2f(u.y);
        acc = make_float4(w * fa.x, w * fa.y, w * fb.x, w * fb.y);
    }

    int p = beg;
    for (; p + 2 <= end; p += 2) {
        int sa = g_esrc[p];
        int sb = g_esrc[p + 1];
        float2 ea = g_e2s[sa];
        float2 eb = g_e2s[sb];
        uint2 ua = make_uint2(0u, 0u), ub = make_uint2(0u, 0u);
        if (act) {
            ua = *(const uint2*)(g_g2h + sa * 20 + r * 2);
            ub = *(const uint2*)(g_g2h + sb * 20 + r * 2);
        }
        float wa = wmax(ea, dd);
        float wb = wmax(eb, dd);
        denom += wa + wb;
        if (act) {
            float2 f;
            f = h2f(ua.x); acc.x += wa * f.x; acc.y += wa * f.y;
            f = h2f(ua.y); acc.z += wa * f.x; acc.w += wa * f.y;
            f = h2f(ub.x); acc.x += wb * f.x; acc.y += wb * f.y;
            f = h2f(ub.y); acc.z += wb * f.x; acc.w += wb * f.y;
        }
    }
    if (p < end) {
        int src = g_esrc[p];
        float wi = wmax(g_e2s[src], dd);
        denom += wi;
        if (act) {
            uint2 u = *(const uint2*)(g_g2h + src * 20 + r * 2);
            float2 fa = h2f(u.x), fb = h2f(u.y);
            acc.x += wi * fa.x; acc.y += wi * fa.y; acc.z += wi * fb.x; acc.w += wi * fb.y;
        }
    }

    float inv = 1.0f / denom;
    float4 v = make_float4(-3.0e38f, -3.0e38f, -3.0e38f, -3.0e38f);
    if (act) {
        float4 bb = ((const float4*)b2)[r];
        v = make_float4(acc.x * inv + bb.x, acc.y * inv + bb.y,
                        acc.z * inv + bb.z, acc.w * inv + bb.w);
    }

    // log_softmax across the 10 active lanes (width-16 reductions)
    float m = fmaxf(fmaxf(v.x, v.y), fmaxf(v.z, v.w));
#pragma unroll
    for (int o = 8; o; o >>= 1) m = fmaxf(m, __shfl_xor_sync(0xffffffffu, m, o, 16));
    float s = 0.f;
    if (act) s = expf(v.x - m) + expf(v.y - m) + expf(v.z - m) + expf(v.w - m);
#pragma unroll
    for (int o = 8; o; o >>= 1) s += __shfl_xor_sync(0xffffffffu, s, o, 16);
    float lse = m + logf(s);

    if (act && n < N) {
        float4 o4 = make_float4(v.x - lse, v.y - lse, v.z - lse, v.w - lse);
        ((float4*)(out + (long long)n * OUT2))[r] = o4;
    }
}

// ---------------------------------------------------------------------------
extern "C" void kernel_launch(void* const* d_in, const int* in_sizes, int n_in,
                              void* d_out, int out_size)
{
    const float* x     = (const float*)d_in[0];
    const void*  ei    = d_in[1];
    const float* W1    = (const float*)d_in[2];
    const float* atts1 = (const float*)d_in[3];
    const float* attd1 = (const float*)d_in[4];
    const float* b1    = (const float*)d_in[5];
    const float* W2    = (const float*)d_in[6];
    const float* atts2 = (const float*)d_in[7];
    const float* attd2 = (const float*)d_in[8];
    const float* b2    = (const float*)d_in[9];

    int N = in_sizes[0] / IN_F;
    int E = in_sizes[1] / 2;
    if (N > N_CAP) N = N_CAP;
    if (E > E_CAP) E = E_CAP;
    const int nb_scan = (N + 511) / 512;

    k0_detect<<<1, 256>>>((const unsigned int*)ei, 2 * E);
    k_zero<<<(N + 255) / 256, 256>>>(N);
    k_hist<<<(E + 255) / 256, 256>>>(ei, E);
    k_scan1<<<nb_scan, 512>>>(N);
    k_scan2<<<1, 256>>>(nb_scan);
    k_scan3<<<(N + 255) / 256, 256>>>(N);
    k_scatter<<<(E + 255) / 256, 256>>>(ei, E);

    k1_gemm_attn<<<(N + 127) / 128, 256>>>(x, W1, atts1, attd1, N);
    kL1_gather<<<(N + 31) / 32, 256>>>(W2, b1, atts2, attd2, N);
    kL2_gather<<<(N + 15) / 16, 256>>>(b2, (float*)d_out, N);
}

// round 14
// speedup vs baseline: 1.5219x; 1.0037x over previous
#include <cuda_runtime.h>
#include <cuda_fp16.h>
#include <cuda_bf16.h>

// ---------------------------------------------------------------------------
// GATnet 2-layer GAT, N=100000, E=1600000, IN=128, L1: 8x8 concat, ELU,
// L2: 1x40, log_softmax.
// R14: SAME kernels as R13 (best: 274.46us). Launch order changed so that
// k1_gemm_attn sits at launch index 3 -- the slot ncu empirically captures --
// to finally attribute the ~140us my per-kernel models cannot explain.
// (k1 is independent of the CSR chain, so the reorder is semantics-free.)
// ---------------------------------------------------------------------------

#define N_CAP 100000
#define E_CAP 1600000
#define IN_F  128
#define HC1   64
#define H1    8
#define OUT2  40
#define NEG_SLOPE 0.2f

// Scratch (static device globals)
__device__ __align__(16) __half2 g_h1h[N_CAP * 32];   // [N][64] as half2 (128B/node)
__device__ float2 g_e1s[N_CAP * H1];   // (exp(as), exp(.2 as)) layer 1
__device__ float2 g_e1d[N_CAP * H1];   // (exp(ad), exp(.2 ad)) layer 1
__device__ __align__(16) __half2 g_g2h[N_CAP * 20];   // [N][40] as half2 (80B/node)
__device__ float2 g_e2s[N_CAP];        // layer 2 src factors
__device__ float2 g_e2d[N_CAP];        // layer 2 dst factors
__device__ int    g_esrc[E_CAP];
__device__ int    g_deg[N_CAP];
__device__ int    g_rowptr[N_CAP];
__device__ int    g_cursor[N_CAP];
__device__ int    g_blksum[256];
__device__ int    g_is64;

__device__ __forceinline__ float2 h2f(unsigned int u) {
    __half2 h = *reinterpret_cast<__half2*>(&u);
    return __half22float2(h);
}

__device__ __forceinline__ unsigned long long pk2(float lo, float hi) {
    unsigned long long r;
    asm("mov.b64 %0, {%1, %2};" : "=l"(r) : "f"(lo), "f"(hi));
    return r;
}
__device__ __forceinline__ void unpk2(float& lo, float& hi, unsigned long long v) {
    asm("mov.b64 {%0, %1}, %2;" : "=f"(lo), "=f"(hi) : "l"(v));
}
__device__ __forceinline__ unsigned long long ffma2(
    unsigned long long a, unsigned long long b, unsigned long long c) {
    unsigned long long d;
    asm("fma.rn.f32x2 %0, %1, %2, %3;" : "=l"(d) : "l"(a), "l"(b), "l"(c));
    return d;
}

// w = exp(lrelu(a_s + a_d)) = max(exp(as)exp(ad), exp(.2as)exp(.2ad))
__device__ __forceinline__ float wmax(float2 s, float2 d) {
    return fmaxf(s.x * d.x, s.y * d.y);
}

// ---------------------------------------------------------------------------
// K0: edge-index dtype detect (int64 stored little-endian => odd words all 0)
// ---------------------------------------------------------------------------
__global__ void k0_detect(const unsigned int* ei32, int nwords) {
    __shared__ int any_nz;
    if (threadIdx.x == 0) any_nz = 0;
    __syncthreads();
    int samples = 2048;
    if (samples * 2 > nwords) samples = nwords / 2;
    for (int i = threadIdx.x; i < samples; i += 256)
        if (ei32[2 * i + 1] != 0u) any_nz = 1;
    __syncthreads();
    if (threadIdx.x == 0) g_is64 = (any_nz == 0) ? 1 : 0;
}

// ---------------------------------------------------------------------------
// CSR construction (multi-kernel, no grid barrier — proven safe)
// ---------------------------------------------------------------------------
__global__ __launch_bounds__(256) void k_zero(int N) {
    int i = blockIdx.x * 256 + threadIdx.x;
    if (i < N) g_deg[i] = 0;
}

__global__ __launch_bounds__(256) void k_hist(const void* ei, int E) {
    int i = blockIdx.x * 256 + threadIdx.x;
    if (i >= E) return;
    int dst = g_is64 ? (int)((const long long*)ei)[E + i] : ((const int*)ei)[E + i];
    atomicAdd(&g_deg[dst], 1);
}

__global__ __launch_bounds__(512) void k_scan1(int N) {
    __shared__ int wsum[16];
    int i = blockIdx.x * 512 + threadIdx.x;
    int v = (i < N) ? g_deg[i] : 0;
    int lane = threadIdx.x & 31, warp = threadIdx.x >> 5;
    int x = v;
#pragma unroll
    for (int o = 1; o < 32; o <<= 1) {
        int t = __shfl_up_sync(0xffffffffu, x, o);
        if (lane >= o) x += t;
    }
    if (lane == 31) wsum[warp] = x;
    __syncthreads();
    if (warp == 0) {
        int ws = (lane < 16) ? wsum[lane] : 0;
#pragma unroll
        for (int o = 1; o < 16; o <<= 1) {
            int t = __shfl_up_sync(0xffffffffu, ws, o);
            if (lane >= o) ws += t;
        }
        if (lane < 16) wsum[lane] = ws;
    }
    __syncthreads();
    int base = warp ? wsum[warp - 1] : 0;
    if (i < N) g_rowptr[i] = base + x - v;   // exclusive
    if (threadIdx.x == 511) g_blksum[blockIdx.x] = base + x;
}

__global__ __launch_bounds__(256) void k_scan2(int nb) {
    __shared__ int wsum[8];
    int lane = threadIdx.x & 31, warp = threadIdx.x >> 5;
    int v = (threadIdx.x < nb) ? g_blksum[threadIdx.x] : 0;
    int x = v;
#pragma unroll
    for (int o = 1; o < 32; o <<= 1) {
        int t = __shfl_up_sync(0xffffffffu, x, o);
        if (lane >= o) x += t;
    }
    if (lane == 31) wsum[warp] = x;
    __syncthreads();
    if (warp == 0) {
        int ws = (lane < 8) ? wsum[lane] : 0;
#pragma unroll
        for (int o = 1; o < 8; o <<= 1) {
            int t = __shfl_up_sync(0xffffffffu, ws, o);
            if (lane >= o) ws += t;
        }
        if (lane < 8) wsum[lane] = ws;
    }
    __syncthreads();
    int base = warp ? wsum[warp - 1] : 0;
    if (threadIdx.x < nb) g_blksum[threadIdx.x] = base + x - v;   // exclusive
}

__global__ __launch_bounds__(256) void k_scan3(int N) {
    int i = blockIdx.x * 256 + threadIdx.x;
    if (i >= N) return;
    int r = g_rowptr[i] + g_blksum[i >> 9];
    g_rowptr[i] = r;
    g_cursor[i] = r;
}

__global__ __launch_bounds__(256) void k_scatter(const void* ei, int E) {
    int i = blockIdx.x * 256 + threadIdx.x;
    if (i >= E) return;
    int src, dst;
    if (g_is64) {
        src = (int)((const long long*)ei)[i];
        dst = (int)((const long long*)ei)[E + i];
    } else {
        src = ((const int*)ei)[i];
        dst = ((const int*)ei)[E + i];
    }
    int pos = atomicAdd(&g_cursor[dst], 1);
    g_esrc[pos] = src;
}

// ---------------------------------------------------------------------------
// K1: h1 = x @ W1 (f32x2 packed FMA); exp-factor pairs for layer-1 attention;
// store h1 fp16. 256 thr -> 128 nodes x 64 outs; thread: 2 nodes x 16 outs.
// ---------------------------------------------------------------------------
__global__ __launch_bounds__(256) void k1_gemm_attn(
    const float* __restrict__ x, const float* __restrict__ W1,
    const float* __restrict__ atts, const float* __restrict__ attd, int N)
{
    __shared__ __align__(16) float Ws[IN_F * HC1];   // 32KB
    __shared__ float s_as[HC1], s_ad[HC1];
    for (int i = threadIdx.x; i < IN_F * HC1; i += 256) Ws[i] = W1[i];
    if (threadIdx.x < HC1) { s_as[threadIdx.x] = atts[threadIdx.x]; s_ad[threadIdx.x] = attd[threadIdx.x]; }
    __syncthreads();

    const int jq = threadIdx.x & 3;
    const int j0 = jq * 16;
    const int pr = threadIdx.x >> 2;
    const int n0 = blockIdx.x * 128 + pr * 2;
    const int n1 = n0 + 1;
    const bool v0 = n0 < N, v1 = n1 < N;

    const float4* xp0 = (const float4*)(x + (long long)(v0 ? n0 : 0) * IN_F);
    const float4* xp1 = (const float4*)(x + (long long)(v1 ? n1 : 0) * IN_F);

    unsigned long long a0p[8], a1p[8];
    const unsigned long long Z = pk2(0.f, 0.f);
#pragma unroll
    for (int i = 0; i < 8; i++) { a0p[i] = Z; a1p[i] = Z; }

#pragma unroll 8
    for (int k4 = 0; k4 < IN_F / 4; k4++) {
        float4 xa = xp0[k4];
        float4 xb = xp1[k4];
        const float* wrow = &Ws[k4 * 4 * HC1 + j0];
#pragma unroll
        for (int kk = 0; kk < 4; kk++) {
            float xav = (&xa.x)[kk];
            float xbv = (&xb.x)[kk];
            unsigned long long xap = pk2(xav, xav);
            unsigned long long xbp = pk2(xbv, xbv);
#pragma unroll
            for (int jj = 0; jj < 4; jj++) {
                ulonglong2 w2 = *(const ulonglong2*)(wrow + kk * HC1 + jj * 4);
                a0p[jj*2+0] = ffma2(xap, w2.x, a0p[jj*2+0]);
                a0p[jj*2+1] = ffma2(xap, w2.y, a0p[jj*2+1]);
                a1p[jj*2+0] = ffma2(xbp, w2.x, a1p[jj*2+0]);
                a1p[jj*2+1] = ffma2(xbp, w2.y, a1p[jj*2+1]);
            }
        }
    }

    const int h0 = j0 >> 3;
#pragma unroll
    for (int sel = 0; sel < 2; sel++) {
        const bool valid = sel ? v1 : v0;
        if (!valid) continue;
        const int n = sel ? n1 : n0;
        unsigned long long* ap = sel ? a1p : a0p;
        float acc[16];
#pragma unroll
        for (int i = 0; i < 8; i++) unpk2(acc[2*i], acc[2*i+1], ap[i]);

        float as0 = 0.f, ad0 = 0.f, as1 = 0.f, ad1 = 0.f;
#pragma unroll
        for (int c = 0; c < 8; c++) {
            as0 += acc[c]     * s_as[h0 * 8 + c];
            ad0 += acc[c]     * s_ad[h0 * 8 + c];
            as1 += acc[8 + c] * s_as[(h0 + 1) * 8 + c];
            ad1 += acc[8 + c] * s_ad[(h0 + 1) * 8 + c];
        }
        g_e1s[n * H1 + h0]     = make_float2(__expf(as0), __expf(NEG_SLOPE * as0));
        g_e1s[n * H1 + h0 + 1] = make_float2(__expf(as1), __expf(NEG_SLOPE * as1));
        g_e1d[n * H1 + h0]     = make_float2(__expf(ad0), __expf(NEG_SLOPE * ad0));
        g_e1d[n * H1 + h0 + 1] = make_float2(__expf(ad1), __expf(NEG_SLOPE * ad1));

        union { __half2 h[8]; uint4 u[2]; } cv;
#pragma unroll
        for (int q = 0; q < 8; q++) cv.h[q] = __floats2half2_rn(acc[2*q], acc[2*q+1]);
        uint4* hp = (uint4*)(g_h1h + n * 32 + jq * 8);
        hp[0] = cv.u[0];
        hp[1] = cv.u[1];
    }
}

// ---------------------------------------------------------------------------
// KL1: fused layer-1 aggregate (exp-free weights, fp16 payload) + normalize +
//      ELU + h2@W2 + layer-2 exp factors. 8 lanes/node, 32 nodes/block.
// ---------------------------------------------------------------------------
__global__ __launch_bounds__(256) void kL1_gather(
    const float* __restrict__ W2, const float* __restrict__ b1,
    const float* __restrict__ atts2, const float* __restrict__ attd2, int N)
{
    __shared__ float W2s[HC1 * OUT2];   // 10.2KB
    __shared__ float b1s[HC1], as2s[OUT2], ad2s[OUT2];
    for (int i = threadIdx.x; i < HC1 * OUT2; i += 256) W2s[i] = W2[i];
    if (threadIdx.x < HC1) b1s[threadIdx.x] = b1[threadIdx.x];
    if (threadIdx.x < OUT2) { as2s[threadIdx.x] = atts2[threadIdx.x]; ad2s[threadIdx.x] = attd2[threadIdx.x]; }
    __syncthreads();

    const int r = threadIdx.x & 7;
    const int n = blockIdx.x * 32 + (threadIdx.x >> 3);
    const int nc = (n < N) ? n : 0;

    const float2 d12 = g_e1d[nc * H1 + r];   // dst factors, hoisted
    const int beg = g_rowptr[nc];
    const int end = beg + g_deg[nc];

    // self-loop
    float w = wmax(g_e1s[nc * H1 + r], d12);
    float denom = w;
    float acc[8];
    {
        uint4 u = *(const uint4*)(g_h1h + nc * 32 + r * 4);
        float2 f0 = h2f(u.x), f1 = h2f(u.y), f2 = h2f(u.z), f3 = h2f(u.w);
        acc[0] = w * f0.x; acc[1] = w * f0.y; acc[2] = w * f1.x; acc[3] = w * f1.y;
        acc[4] = w * f2.x; acc[5] = w * f2.y; acc[6] = w * f3.x; acc[7] = w * f3.y;
    }

    int p = beg;
    for (; p + 2 <= end; p += 2) {
        int sa = g_esrc[p];
        int sb = g_esrc[p + 1];
        float2 ea = g_e1s[sa * H1 + r];
        float2 eb = g_e1s[sb * H1 + r];
        uint4 ua = *(const uint4*)(g_h1h + sa * 32 + r * 4);
        uint4 ub = *(const uint4*)(g_h1h + sb * 32 + r * 4);
        float wa = wmax(ea, d12);
        float wb = wmax(eb, d12);
        denom += wa + wb;
        float2 f;
        f = h2f(ua.x); acc[0] += wa * f.x; acc[1] += wa * f.y;
        f = h2f(ua.y); acc[2] += wa * f.x; acc[3] += wa * f.y;
        f = h2f(ua.z); acc[4] += wa * f.x; acc[5] += wa * f.y;
        f = h2f(ua.w); acc[6] += wa * f.x; acc[7] += wa * f.y;
        f = h2f(ub.x); acc[0] += wb * f.x; acc[1] += wb * f.y;
        f = h2f(ub.y); acc[2] += wb * f.x; acc[3] += wb * f.y;
        f = h2f(ub.z); acc[4] += wb * f.x; acc[5] += wb * f.y;
        f = h2f(ub.w); acc[6] += wb * f.x; acc[7] += wb * f.y;
    }
    if (p < end) {
        int src = g_esrc[p];
        float wi = wmax(g_e1s[src * H1 + r], d12);
        denom += wi;
        uint4 u = *(const uint4*)(g_h1h + src * 32 + r * 4);
        float2 f;
        f = h2f(u.x); acc[0] += wi * f.x; acc[1] += wi * f.y;
        f = h2f(u.y); acc[2] += wi * f.x; acc[3] += wi * f.y;
        f = h2f(u.z); acc[4] += wi * f.x; acc[5] += wi * f.y;
        f = h2f(u.w); acc[6] += wi * f.x; acc[7] += wi * f.y;
    }

    // h2 = elu(acc/denom + b1)
    float inv = 1.0f / denom;
    float h2r[8];
    {
        const float* bb = &b1s[r * 8];
#pragma unroll
        for (int c = 0; c < 8; c++) {
            float v = acc[c] * inv + bb[c];
            h2r[c] = v > 0.f ? v : expm1f(v);
        }
    }

    // g = h2 @ W2 (width-8 shuffle GEMM); lane r owns cols r, r+8, ..., r+32
    float acc2[5] = {0.f, 0.f, 0.f, 0.f, 0.f};
#pragma unroll
    for (int k = 0; k < HC1; k++) {
        float hk = __shfl_sync(0xffffffffu, h2r[k & 7], k >> 3, 8);
#pragma unroll
        for (int i = 0; i < 5; i++) acc2[i] += hk * W2s[k * OUT2 + r + 8 * i];
    }

    float as = 0.f, ad = 0.f;
#pragma unroll
    for (int i = 0; i < 5; i++) { as += acc2[i] * as2s[r + 8 * i]; ad += acc2[i] * ad2s[r + 8 * i]; }
#pragma unroll
    for (int o = 4; o; o >>= 1) {
        as += __shfl_xor_sync(0xffffffffu, as, o, 8);
        ad += __shfl_xor_sync(0xffffffffu, ad, o, 8);
    }

    // pack g2 to half2: even lane r supplies lo (col r+8i), lane r+1 the hi
    float hi_[5];
#pragma unroll
    for (int i = 0; i < 5; i++) hi_[i] = __shfl_xor_sync(0xffffffffu, acc2[i], 1, 8);

    if (n < N) {
        if (r == 0) {
            g_e2s[n] = make_float2(__expf(as), __expf(NEG_SLOPE * as));
            g_e2d[n] = make_float2(__expf(ad), __expf(NEG_SLOPE * ad));
        }
        if ((r & 1) == 0) {
            __half2* gp = g_g2h + n * 20;
#pragma unroll
            for (int i = 0; i < 5; i++)
                gp[(r >> 1) + 4 * i] = __floats2half2_rn(acc2[i], hi_[i]);
        }
    }
}

// ---------------------------------------------------------------------------
// KL2: fused layer-2 aggregate (exp-free weights, fp16 payload) + normalize +
//      bias + log_softmax. 16 lanes/node; lanes 0..9 own 4 channels.
// ---------------------------------------------------------------------------
__global__ __launch_bounds__(256) void kL2_gather(
    const float* __restrict__ b2, float* __restrict__ out, int N)
{
    const int r = threadIdx.x & 15;
    const int n = blockIdx.x * 16 + (threadIdx.x >> 4);
    const int nc = (n < N) ? n : 0;
    const bool act = (r < 10);

    const float2 dd = g_e2d[nc];   // dst factors, hoisted
    const int beg = g_rowptr[nc];
    const int end = beg + g_deg[nc];

    // self-loop
    float w = wmax(g_e2s[nc], dd);
    float denom = w;
    float4 acc = make_float4(0.f, 0.f, 0.f, 0.f);
    if (act) {
        uint2 u = *(const uint2*)(g_g2h + nc * 20 + r * 2);
        float2 fa = h2f(u.x), fb = h2f(u.y);
        acc = make_float4(w * fa.x, w * fa.y, w * fb.x, w * fb.y);
    }

    int p = beg;
    for (; p + 2 <= end; p += 2) {
        int sa = g_esrc[p];
        int sb = g_esrc[p + 1];
        float2 ea = g_e2s[sa];
        float2 eb = g_e2s[sb];
        uint2 ua = make_uint2(0u, 0u), ub = make_uint2(0u, 0u);
        if (act) {
            ua = *(const uint2*)(g_g2h + sa * 20 + r * 2);
            ub = *(const uint2*)(g_g2h + sb * 20 + r * 2);
        }
        float wa = wmax(ea, dd);
        float wb = wmax(eb, dd);
        denom += wa + wb;
        if (act) {
            float2 f;
            f = h2f(ua.x); acc.x += wa * f.x; acc.y += wa * f.y;
            f = h2f(ua.y); acc.z += wa * f.x; acc.w += wa * f.y;
            f = h2f(ub.x); acc.x += wb * f.x; acc.y += wb * f.y;
            f = h2f(ub.y); acc.z += wb * f.x; acc.w += wb * f.y;
        }
    }
    if (p < end) {
        int src = g_esrc[p];
        float wi = wmax(g_e2s[src], dd);
        denom += wi;
        if (act) {
            uint2 u = *(const uint2*)(g_g2h + src * 20 + r * 2);
            float2 fa = h2f(u.x), fb = h2f(u.y);
            acc.x += wi * fa.x; acc.y += wi * fa.y; acc.z += wi * fb.x; acc.w += wi * fb.y;
        }
    }

    float inv = 1.0f / denom;
    float4 v = make_float4(-3.0e38f, -3.0e38f, -3.0e38f, -3.0e38f);
    if (act) {
        float4 bb = ((const float4*)b2)[r];
        v = make_float4(acc.x * inv + bb.x, acc.y * inv + bb.y,
                        acc.z * inv + bb.z, acc.w * inv + bb.w);
    }

    // log_softmax across the 10 active lanes (width-16 reductions)
    float m = fmaxf(fmaxf(v.x, v.y), fmaxf(v.z, v.w));
#pragma unroll
    for (int o = 8; o; o >>= 1) m = fmaxf(m, __shfl_xor_sync(0xffffffffu, m, o, 16));
    float s = 0.f;
    if (act) s = expf(v.x - m) + expf(v.y - m) + expf(v.z - m) + expf(v.w - m);
#pragma unroll
    for (int o = 8; o; o >>= 1) s += __shfl_xor_sync(0xffffffffu, s, o, 16);
    float lse = m + logf(s);

    if (act && n < N) {
        float4 o4 = make_float4(v.x - lse, v.y - lse, v.z - lse, v.w - lse);
        ((float4*)(out + (long long)n * OUT2))[r] = o4;
    }
}

// ---------------------------------------------------------------------------
extern "C" void kernel_launch(void* const* d_in, const int* in_sizes, int n_in,
                              void* d_out, int out_size)
{
    const float* x     = (const float*)d_in[0];
    const void*  ei    = d_in[1];
    const float* W1    = (const float*)d_in[2];
    const float* atts1 = (const float*)d_in[3];
    const float* attd1 = (const float*)d_in[4];
    const float* b1    = (const float*)d_in[5];
    const float* W2    = (const float*)d_in[6];
    const float* atts2 = (const float*)d_in[7];
    const float* attd2 = (const float*)d_in[8];
    const float* b2    = (const float*)d_in[9];

    int N = in_sizes[0] / IN_F;
    int E = in_sizes[1] / 2;
    if (N > N_CAP) N = N_CAP;
    if (E > E_CAP) E = E_CAP;
    const int nb_scan = (N + 511) / 512;

    // Launch order chosen so k1_gemm_attn is launch index 3 (the slot ncu
    // captures). k1 is independent of the CSR chain; all dependencies hold:
    // hist needs zero+detect; scan1 needs hist; scatter needs scan3+detect;
    // kL1 needs k1+scatter; kL2 needs kL1.
    k_zero<<<(N + 255) / 256, 256>>>(N);                           // 0
    k0_detect<<<1, 256>>>((const unsigned int*)ei, 2 * E);         // 1
    k_hist<<<(E + 255) / 256, 256>>>(ei, E);                       // 2
    k1_gemm_attn<<<(N + 127) / 128, 256>>>(x, W1, atts1, attd1, N);// 3 <- profiled
    k_scan1<<<nb_scan, 512>>>(N);                                  // 4
    k_scan2<<<1, 256>>>(nb_scan);                                  // 5
    k_scan3<<<(N + 255) / 256, 256>>>(N);                          // 6
    k_scatter<<<(E + 255) / 256, 256>>>(ei, E);                    // 7
    kL1_gather<<<(N + 31) / 32, 256>>>(W2, b1, atts2, attd2, N);   // 8
    kL2_gather<<<(N + 15) / 16, 256>>>(b2, (float*)d_out, N);      // 9
}

// round 15
// speedup vs baseline: 1.8576x; 1.2205x over previous
#include <cuda_runtime.h>
#include <cuda_fp16.h>
#include <cuda_bf16.h>

// ---------------------------------------------------------------------------
// GATnet 2-layer GAT, N=100000, E=1600000, IN=128, L1: 8x8 concat, ELU,
// L2: 1x40, log_softmax.
// R15: k1 re-tiled as outer-product GEMM (xT staged+transposed in smem,
// thread tile 4 nodes x 8 outs, f32x2 FMA with natural b-pairs) -- R14 ncu
// showed k1 = 122.8us, L1(shared)=79% bound, fma only 17%. Everything else
// = R13/R14 (274.5us best path). k1 kept at launch slot 3 for verification.
// ---------------------------------------------------------------------------

#define N_CAP 100000
#define E_CAP 1600000
#define IN_F  128
#define HC1   64
#define H1    8
#define OUT2  40
#define NEG_SLOPE 0.2f
#define NPAD  132   // xT row pitch (floats); 132%4==0 keeps LDS.128 alignment

// Scratch (static device globals)
__device__ __align__(16) __half2 g_h1h[N_CAP * 32];   // [N][64] as half2 (128B/node)
__device__ float2 g_e1s[N_CAP * H1];   // (exp(as), exp(.2 as)) layer 1
__device__ float2 g_e1d[N_CAP * H1];   // (exp(ad), exp(.2 ad)) layer 1
__device__ __align__(16) __half2 g_g2h[N_CAP * 20];   // [N][40] as half2 (80B/node)
__device__ float2 g_e2s[N_CAP];        // layer 2 src factors
__device__ float2 g_e2d[N_CAP];        // layer 2 dst factors
__device__ int    g_esrc[E_CAP];
__device__ int    g_deg[N_CAP];
__device__ int    g_rowptr[N_CAP];
__device__ int    g_cursor[N_CAP];
__device__ int    g_blksum[256];
__device__ int    g_is64;

__device__ __forceinline__ float2 h2f(unsigned int u) {
    __half2 h = *reinterpret_cast<__half2*>(&u);
    return __half22float2(h);
}

__device__ __forceinline__ unsigned long long pk2(float lo, float hi) {
    unsigned long long r;
    asm("mov.b64 %0, {%1, %2};" : "=l"(r) : "f"(lo), "f"(hi));
    return r;
}
__device__ __forceinline__ void unpk2(float& lo, float& hi, unsigned long long v) {
    asm("mov.b64 {%0, %1}, %2;" : "=f"(lo), "=f"(hi) : "l"(v));
}
__device__ __forceinline__ unsigned long long ffma2(
    unsigned long long a, unsigned long long b, unsigned long long c) {
    unsigned long long d;
    asm("fma.rn.f32x2 %0, %1, %2, %3;" : "=l"(d) : "l"(a), "l"(b), "l"(c));
    return d;
}

// w = exp(lrelu(a_s + a_d)) = max(exp(as)exp(ad), exp(.2as)exp(.2ad))
__device__ __forceinline__ float wmax(float2 s, float2 d) {
    return fmaxf(s.x * d.x, s.y * d.y);
}

// ---------------------------------------------------------------------------
// K0: edge-index dtype detect (int64 stored little-endian => odd words all 0)
// ---------------------------------------------------------------------------
__global__ void k0_detect(const unsigned int* ei32, int nwords) {
    __shared__ int any_nz;
    if (threadIdx.x == 0) any_nz = 0;
    __syncthreads();
    int samples = 2048;
    if (samples * 2 > nwords) samples = nwords / 2;
    for (int i = threadIdx.x; i < samples; i += 256)
        if (ei32[2 * i + 1] != 0u) any_nz = 1;
    __syncthreads();
    if (threadIdx.x == 0) g_is64 = (any_nz == 0) ? 1 : 0;
}

// ---------------------------------------------------------------------------
// CSR construction (multi-kernel, no grid barrier — proven safe)
// ---------------------------------------------------------------------------
__global__ __launch_bounds__(256) void k_zero(int N) {
    int i = blockIdx.x * 256 + threadIdx.x;
    if (i < N) g_deg[i] = 0;
}

__global__ __launch_bounds__(256) void k_hist(const void* ei, int E) {
    int i = blockIdx.x * 256 + threadIdx.x;
    if (i >= E) return;
    int dst = g_is64 ? (int)((const long long*)ei)[E + i] : ((const int*)ei)[E + i];
    atomicAdd(&g_deg[dst], 1);
}

__global__ __launch_bounds__(512) void k_scan1(int N) {
    __shared__ int wsum[16];
    int i = blockIdx.x * 512 + threadIdx.x;
    int v = (i < N) ? g_deg[i] : 0;
    int lane = threadIdx.x & 31, warp = threadIdx.x >> 5;
    int x = v;
#pragma unroll
    for (int o = 1; o < 32; o <<= 1) {
        int t = __shfl_up_sync(0xffffffffu, x, o);
        if (lane >= o) x += t;
    }
    if (lane == 31) wsum[warp] = x;
    __syncthreads();
    if (warp == 0) {
        int ws = (lane < 16) ? wsum[lane] : 0;
#pragma unroll
        for (int o = 1; o < 16; o <<= 1) {
            int t = __shfl_up_sync(0xffffffffu, ws, o);
            if (lane >= o) ws += t;
        }
        if (lane < 16) wsum[lane] = ws;
    }
    __syncthreads();
    int base = warp ? wsum[warp - 1] : 0;
    if (i < N) g_rowptr[i] = base + x - v;   // exclusive
    if (threadIdx.x == 511) g_blksum[blockIdx.x] = base + x;
}

__global__ __launch_bounds__(256) void k_scan2(int nb) {
    __shared__ int wsum[8];
    int lane = threadIdx.x & 31, warp = threadIdx.x >> 5;
    int v = (threadIdx.x < nb) ? g_blksum[threadIdx.x] : 0;
    int x = v;
#pragma unroll
    for (int o = 1; o < 32; o <<= 1) {
        int t = __shfl_up_sync(0xffffffffu, x, o);
        if (lane >= o) x += t;
    }
    if (lane == 31) wsum[warp] = x;
    __syncthreads();
    if (warp == 0) {
        int ws = (lane < 8) ? wsum[lane] : 0;
#pragma unroll
        for (int o = 1; o < 8; o <<= 1) {
            int t = __shfl_up_sync(0xffffffffu, ws, o);
            if (lane >= o) ws += t;
        }
        if (lane < 8) wsum[lane] = ws;
    }
    __syncthreads();
    int base = warp ? wsum[warp - 1] : 0;
    if (threadIdx.x < nb) g_blksum[threadIdx.x] = base + x - v;   // exclusive
}

__global__ __launch_bounds__(256) void k_scan3(int N) {
    int i = blockIdx.x * 256 + threadIdx.x;
    if (i >= N) return;
    int r = g_rowptr[i] + g_blksum[i >> 9];
    g_rowptr[i] = r;
    g_cursor[i] = r;
}

__global__ __launch_bounds__(256) void k_scatter(const void* ei, int E) {
    int i = blockIdx.x * 256 + threadIdx.x;
    if (i >= E) return;
    int src, dst;
    if (g_is64) {
        src = (int)((const long long*)ei)[i];
        dst = (int)((const long long*)ei)[E + i];
    } else {
        src = ((const int*)ei)[i];
        dst = ((const int*)ei)[E + i];
    }
    int pos = atomicAdd(&g_cursor[dst], 1);
    g_esrc[pos] = src;
}

// ---------------------------------------------------------------------------
// K1 (v2): h1 = x @ W1 as outer-product GEMM.
// Block: 256 thr, 128 nodes x 64 outs. Thread: 4 nodes x 8 outs (= head og).
// x staged+transposed into smem (16 k per stage); W resident in smem.
// f32x2 FMA: b-pairs natural from LDS.128; a broadcast via mov (alu pipe).
// ---------------------------------------------------------------------------
__global__ __launch_bounds__(256) void k1_gemm_attn(
    const float* __restrict__ x, const float* __restrict__ W1,
    const float* __restrict__ atts, const float* __restrict__ attd, int N)
{
    __shared__ __align__(16) float Ws[IN_F * HC1];   // 32KB, [k][64] row-major
    __shared__ __align__(16) float xT[16 * NPAD];    // 8.4KB, [k%16][node]
    __shared__ float s_as[HC1], s_ad[HC1];
    for (int i = threadIdx.x; i < IN_F * HC1; i += 256) Ws[i] = W1[i];
    if (threadIdx.x < HC1) { s_as[threadIdx.x] = atts[threadIdx.x]; s_ad[threadIdx.x] = attd[threadIdx.x]; }

    const int t  = threadIdx.x;
    const int og = t & 7;          // head / out-group: outs og*8 .. og*8+7
    const int ng = t >> 3;         // node group: nodes ng*4 .. ng*4+3
    const int node_base = blockIdx.x * 128;

    unsigned long long accp[4][4];   // [node][out-pair]
    const unsigned long long Z = pk2(0.f, 0.f);
#pragma unroll
    for (int n = 0; n < 4; n++)
#pragma unroll
        for (int o = 0; o < 4; o++) accp[n][o] = Z;

    const int ld_nd = t >> 2;      // 0..63 (+64 on rep 1)
    const int ld_kq = t & 3;       // 0..3

#pragma unroll 1
    for (int ks = 0; ks < 8; ks++) {
        __syncthreads();
        // stage: load x[*, ks*16 .. ks*16+15] transposed into xT
#pragma unroll
        for (int rep = 0; rep < 2; rep++) {
            int nd = ld_nd + rep * 64;
            int gn = node_base + nd;
            float4 v = make_float4(0.f, 0.f, 0.f, 0.f);
            if (gn < N) v = ((const float4*)x)[gn * (IN_F / 4) + ks * 4 + ld_kq];
            xT[(ld_kq * 4 + 0) * NPAD + nd] = v.x;
            xT[(ld_kq * 4 + 1) * NPAD + nd] = v.y;
            xT[(ld_kq * 4 + 2) * NPAD + nd] = v.z;
            xT[(ld_kq * 4 + 3) * NPAD + nd] = v.w;
        }
        __syncthreads();

#pragma unroll
        for (int k = 0; k < 16; k++) {
            float4 a = *(const float4*)&xT[k * NPAD + ng * 4];
            const ulonglong2* bp = (const ulonglong2*)&Ws[(ks * 16 + k) * HC1 + og * 8];
            ulonglong2 b01 = bp[0];            // outs (0,1),(2,3)
            ulonglong2 b23 = bp[1];            // outs (4,5),(6,7)
            unsigned long long a0 = pk2(a.x, a.x);
            unsigned long long a1 = pk2(a.y, a.y);
            unsigned long long a2 = pk2(a.z, a.z);
            unsigned long long a3 = pk2(a.w, a.w);
            accp[0][0] = ffma2(a0, b01.x, accp[0][0]);
            accp[0][1] = ffma2(a0, b01.y, accp[0][1]);
            accp[0][2] = ffma2(a0, b23.x, accp[0][2]);
            accp[0][3] = ffma2(a0, b23.y, accp[0][3]);
            accp[1][0] = ffma2(a1, b01.x, accp[1][0]);
            accp[1][1] = ffma2(a1, b01.y, accp[1][1]);
            accp[1][2] = ffma2(a1, b23.x, accp[1][2]);
            accp[1][3] = ffma2(a1, b23.y, accp[1][3]);
            accp[2][0] = ffma2(a2, b01.x, accp[2][0]);
            accp[2][1] = ffma2(a2, b01.y, accp[2][1]);
            accp[2][2] = ffma2(a2, b23.x, accp[2][2]);
            accp[2][3] = ffma2(a2, b23.y, accp[2][3]);
            accp[3][0] = ffma2(a3, b01.x, accp[3][0]);
            accp[3][1] = ffma2(a3, b01.y, accp[3][1]);
            accp[3][2] = ffma2(a3, b23.x, accp[3][2]);
            accp[3][3] = ffma2(a3, b23.y, accp[3][3]);
        }
    }

    // Epilogue: per node, attention dots for head og + fp16 h1 store.
#pragma unroll
    for (int n = 0; n < 4; n++) {
        int node = node_base + ng * 4 + n;
        if (node >= N) break;
        float h[8];
#pragma unroll
        for (int o = 0; o < 4; o++) unpk2(h[2 * o], h[2 * o + 1], accp[n][o]);

        float as = 0.f, ad = 0.f;
#pragma unroll
        for (int c = 0; c < 8; c++) {
            as += h[c] * s_as[og * 8 + c];
            ad += h[c] * s_ad[og * 8 + c];
        }
        g_e1s[node * H1 + og] = make_float2(__expf(as), __expf(NEG_SLOPE * as));
        g_e1d[node * H1 + og] = make_float2(__expf(ad), __expf(NEG_SLOPE * ad));

        union { __half2 hh[4]; uint4 u; } cv;
#pragma unroll
        for (int c = 0; c < 4; c++) cv.hh[c] = __floats2half2_rn(h[2 * c], h[2 * c + 1]);
        *(uint4*)(g_h1h + node * 32 + og * 4) = cv.u;
    }
}

// ---------------------------------------------------------------------------
// KL1: fused layer-1 aggregate (exp-free weights, fp16 payload) + normalize +
//      ELU + h2@W2 + layer-2 exp factors. 8 lanes/node, 32 nodes/block.
// ---------------------------------------------------------------------------
__global__ __launch_bounds__(256) void kL1_gather(
    const float* __restrict__ W2, const float* __restrict__ b1,
    const float* __restrict__ atts2, const float* __restrict__ attd2, int N)
{
    __shared__ float W2s[HC1 * OUT2];   // 10.2KB
    __shared__ float b1s[HC1], as2s[OUT2], ad2s[OUT2];
    for (int i = threadIdx.x; i < HC1 * OUT2; i += 256) W2s[i] = W2[i];
    if (threadIdx.x < HC1) b1s[threadIdx.x] = b1[threadIdx.x];
    if (threadIdx.x < OUT2) { as2s[threadIdx.x] = atts2[threadIdx.x]; ad2s[threadIdx.x] = attd2[threadIdx.x]; }
    __syncthreads();

    const int r = threadIdx.x & 7;
    const int n = blockIdx.x * 32 + (threadIdx.x >> 3);
    const int nc = (n < N) ? n : 0;

    const float2 d12 = g_e1d[nc * H1 + r];   // dst factors, hoisted
    const int beg = g_rowptr[nc];
    const int end = beg + g_deg[nc];

    // self-loop
    float w = wmax(g_e1s[nc * H1 + r], d12);
    float denom = w;
    float acc[8];
    {
        uint4 u = *(const uint4*)(g_h1h + nc * 32 + r * 4);
        float2 f0 = h2f(u.x), f1 = h2f(u.y), f2 = h2f(u.z), f3 = h2f(u.w);
        acc[0] = w * f0.x; acc[1] = w * f0.y; acc[2] = w * f1.x; acc[3] = w * f1.y;
        acc[4] = w * f2.x; acc[5] = w * f2.y; acc[6] = w * f3.x; acc[7] = w * f3.y;
    }

    int p = beg;
    for (; p + 2 <= end; p += 2) {
        int sa = g_esrc[p];
        int sb = g_esrc[p + 1];
        float2 ea = g_e1s[sa * H1 + r];
        float2 eb = g_e1s[sb * H1 + r];
        uint4 ua = *(const uint4*)(g_h1h + sa * 32 + r * 4);
        uint4 ub = *(const uint4*)(g_h1h + sb * 32 + r * 4);
        float wa = wmax(ea, d12);
        float wb = wmax(eb, d12);
        denom += wa + wb;
        float2 f;
        f = h2f(ua.x); acc[0] += wa * f.x; acc[1] += wa * f.y;
        f = h2f(ua.y); acc[2] += wa * f.x; acc[3] += wa * f.y;
        f = h2f(ua.z); acc[4] += wa * f.x; acc[5] += wa * f.y;
        f = h2f(ua.w); acc[6] += wa * f.x; acc[7] += wa * f.y;
        f = h2f(ub.x); acc[0] += wb * f.x; acc[1] += wb * f.y;
        f = h2f(ub.y); acc[2] += wb * f.x; acc[3] += wb * f.y;
        f = h2f(ub.z); acc[4] += wb * f.x; acc[5] += wb * f.y;
        f = h2f(ub.w); acc[6] += wb * f.x; acc[7] += wb * f.y;
    }
    if (p < end) {
        int src = g_esrc[p];
        float wi = wmax(g_e1s[src * H1 + r], d12);
        denom += wi;
        uint4 u = *(const uint4*)(g_h1h + src * 32 + r * 4);
        float2 f;
        f = h2f(u.x); acc[0] += wi * f.x; acc[1] += wi * f.y;
        f = h2f(u.y); acc[2] += wi * f.x; acc[3] += wi * f.y;
        f = h2f(u.z); acc[4] += wi * f.x; acc[5] += wi * f.y;
        f = h2f(u.w); acc[6] += wi * f.x; acc[7] += wi * f.y;
    }

    // h2 = elu(acc/denom + b1)
    float inv = 1.0f / denom;
    float h2r[8];
    {
        const float* bb = &b1s[r * 8];
#pragma unroll
        for (int c = 0; c < 8; c++) {
            float v = acc[c] * inv + bb[c];
            h2r[c] = v > 0.f ? v : expm1f(v);
        }
    }

    // g = h2 @ W2 (width-8 shuffle GEMM); lane r owns cols r, r+8, ..., r+32
    float acc2[5] = {0.f, 0.f, 0.f, 0.f, 0.f};
#pragma unroll
    for (int k = 0; k < HC1; k++) {
        float hk = __shfl_sync(0xffffffffu, h2r[k & 7], k >> 3, 8);
#pragma unroll
        for (int i = 0; i < 5; i++) acc2[i] += hk * W2s[k * OUT2 + r + 8 * i];
    }

    float as = 0.f, ad = 0.f;
#pragma unroll
    for (int i = 0; i < 5; i++) { as += acc2[i] * as2s[r + 8 * i]; ad += acc2[i] * ad2s[r + 8 * i]; }
#pragma unroll
    for (int o = 4; o; o >>= 1) {
        as += __shfl_xor_sync(0xffffffffu, as, o, 8);
        ad += __shfl_xor_sync(0xffffffffu, ad, o, 8);
    }

    // pack g2 to half2: even lane r supplies lo (col r+8i), lane r+1 the hi
    float hi_[5];
#pragma unroll
    for (int i = 0; i < 5; i++) hi_[i] = __shfl_xor_sync(0xffffffffu, acc2[i], 1, 8);

    if (n < N) {
        if (r == 0) {
            g_e2s[n] = make_float2(__expf(as), __expf(NEG_SLOPE * as));
            g_e2d[n] = make_float2(__expf(ad), __expf(NEG_SLOPE * ad));
        }
        if ((r & 1) == 0) {
            __half2* gp = g_g2h + n * 20;
#pragma unroll
            for (int i = 0; i < 5; i++)
                gp[(r >> 1) + 4 * i] = __floats2half2_rn(acc2[i], hi_[i]);
        }
    }
}

// ---------------------------------------------------------------------------
// KL2: fused layer-2 aggregate (exp-free weights, fp16 payload) + normalize +
//      bias + log_softmax. 16 lanes/node; lanes 0..9 own 4 channels.
// ---------------------------------------------------------------------------
__global__ __launch_bounds__(256) void kL2_gather(
    const float* __restrict__ b2, float* __restrict__ out, int N)
{
    const int r = threadIdx.x & 15;
    const int n = blockIdx.x * 16 + (threadIdx.x >> 4);
    const int nc = (n < N) ? n : 0;
    const bool act = (r < 10);

    const float2 dd = g_e2d[nc];   // dst factors, hoisted
    const int beg = g_rowptr[nc];
    const int end = beg + g_deg[nc];

    // self-loop
    float w = wmax(g_e2s[nc], dd);
    float denom = w;
    float4 acc = make_float4(0.f, 0.f, 0.f, 0.f);
    if (act) {
        uint2 u = *(const uint2*)(g_g2h + nc * 20 + r * 2);
        float2 fa = h2f(u.x), fb = h2f(u.y);
        acc = make_float4(w * fa.x, w * fa.y, w * fb.x, w * fb.y);
    }

    int p = beg;
    for (; p + 2 <= end; p += 2) {
        int sa = g_esrc[p];
        int sb = g_esrc[p + 1];
        float2 ea = g_e2s[sa];
        float2 eb = g_e2s[sb];
        uint2 ua = make_uint2(0u, 0u), ub = make_uint2(0u, 0u);
        if (act) {
            ua = *(const uint2*)(g_g2h + sa * 20 + r * 2);
            ub = *(const uint2*)(g_g2h + sb * 20 + r * 2);
        }
        float wa = wmax(ea, dd);
        float wb = wmax(eb, dd);
        denom += wa + wb;
        if (act) {
            float2 f;
            f = h2f(ua.x); acc.x += wa * f.x; acc.y += wa * f.y;
            f = h2f(ua.y); acc.z += wa * f.x; acc.w += wa * f.y;
            f = h2f(ub.x); acc.x += wb * f.x; acc.y += wb * f.y;
            f = h2f(ub.y); acc.z += wb * f.x; acc.w += wb * f.y;
        }
    }
    if (p < end) {
        int src = g_esrc[p];
        float wi = wmax(g_e2s[src], dd);
        denom += wi;
        if (act) {
            uint2 u = *(const uint2*)(g_g2h + src * 20 + r * 2);
            float2 fa = h2f(u.x), fb = h2f(u.y);
            acc.x += wi * fa.x; acc.y += wi * fa.y; acc.z += wi * fb.x; acc.w += wi * fb.y;
        }
    }

    float inv = 1.0f / denom;
    float4 v = make_float4(-3.0e38f, -3.0e38f, -3.0e38f, -3.0e38f);
    if (act) {
        float4 bb = ((const float4*)b2)[r];
        v = make_float4(acc.x * inv + bb.x, acc.y * inv + bb.y,
                        acc.z * inv + bb.z, acc.w * inv + bb.w);
    }

    // log_softmax across the 10 active lanes (width-16 reductions)
    float m = fmaxf(fmaxf(v.x, v.y), fmaxf(v.z, v.w));
#pragma unroll
    for (int o = 8; o; o >>= 1) m = fmaxf(m, __shfl_xor_sync(0xffffffffu, m, o, 16));
    float s = 0.f;
    if (act) s = expf(v.x - m) + expf(v.y - m) + expf(v.z - m) + expf(v.w - m);
#pragma unroll
    for (int o = 8; o; o >>= 1) s += __shfl_xor_sync(0xffffffffu, s, o, 16);
    float lse = m + logf(s);

    if (act && n < N) {
        float4 o4 = make_float4(v.x - lse, v.y - lse, v.z - lse, v.w - lse);
        ((float4*)(out + (long long)n * OUT2))[r] = o4;
    }
}

// ---------------------------------------------------------------------------
extern "C" void kernel_launch(void* const* d_in, const int* in_sizes, int n_in,
                              void* d_out, int out_size)
{
    const float* x     = (const float*)d_in[0];
    const void*  ei    = d_in[1];
    const float* W1    = (const float*)d_in[2];
    const float* atts1 = (const float*)d_in[3];
    const float* attd1 = (const float*)d_in[4];
    const float* b1    = (const float*)d_in[5];
    const float* W2    = (const float*)d_in[6];
    const float* atts2 = (const float*)d_in[7];
    const float* attd2 = (const float*)d_in[8];
    const float* b2    = (const float*)d_in[9];

    int N = in_sizes[0] / IN_F;
    int E = in_sizes[1] / 2;
    if (N > N_CAP) N = N_CAP;
    if (E > E_CAP) E = E_CAP;
    const int nb_scan = (N + 511) / 512;

    // k1 kept at launch index 3 (the slot ncu captures) to verify the re-tile.
    k_zero<<<(N + 255) / 256, 256>>>(N);                           // 0
    k0_detect<<<1, 256>>>((const unsigned int*)ei, 2 * E);         // 1
    k_hist<<<(E + 255) / 256, 256>>>(ei, E);                       // 2
    k1_gemm_attn<<<(N + 127) / 128, 256>>>(x, W1, atts1, attd1, N);// 3 <- profiled
    k_scan1<<<nb_scan, 512>>>(N);                                  // 4
    k_scan2<<<1, 256>>>(nb_scan);                                  // 5
    k_scan3<<<(N + 255) / 256, 256>>>(N);                          // 6
    k_scatter<<<(E + 255) / 256, 256>>>(ei, E);                    // 7
    kL1_gather<<<(N + 31) / 32, 256>>>(W2, b1, atts2, attd2, N);   // 8
    kL2_gather<<<(N + 15) / 16, 256>>>(b2, (float*)d_out, N);      // 9
}

// round 16
// speedup vs baseline: 1.8925x; 1.0188x over previous
#include <cuda_runtime.h>
#include <cuda_fp16.h>
#include <cuda_bf16.h>

// ---------------------------------------------------------------------------
// GATnet 2-layer GAT, N=100000, E=1600000, IN=128, L1: 8x8 concat, ELU,
// L2: 1x40, log_softmax.
// R16: k1 tile widened to 8 nodes x 8 outs per thread (256 nodes/block) +
// register prefetch of the next x stage -> 33% fewer LDS wavefronts per FMA
// (R15 ncu: k1 = 75.6us, L1 71.8% binding, fma 28%). Rest = R15 (224.0us).
// ---------------------------------------------------------------------------

#define N_CAP 100000
#define E_CAP 1600000
#define IN_F  128
#define HC1   64
#define H1    8
#define OUT2  40
#define NEG_SLOPE 0.2f
#define NPAD  260   // xT row pitch (floats) for 256 nodes; k*260*4B % 16 == 0

// Scratch (static device globals)
__device__ __align__(16) __half2 g_h1h[N_CAP * 32];   // [N][64] as half2 (128B/node)
__device__ float2 g_e1s[N_CAP * H1];   // (exp(as), exp(.2 as)) layer 1
__device__ float2 g_e1d[N_CAP * H1];   // (exp(ad), exp(.2 ad)) layer 1
__device__ __align__(16) __half2 g_g2h[N_CAP * 20];   // [N][40] as half2 (80B/node)
__device__ float2 g_e2s[N_CAP];        // layer 2 src factors
__device__ float2 g_e2d[N_CAP];        // layer 2 dst factors
__device__ int    g_esrc[E_CAP];
__device__ int    g_deg[N_CAP];
__device__ int    g_rowptr[N_CAP];
__device__ int    g_cursor[N_CAP];
__device__ int    g_blksum[256];
__device__ int    g_is64;

__device__ __forceinline__ float2 h2f(unsigned int u) {
    __half2 h = *reinterpret_cast<__half2*>(&u);
    return __half22float2(h);
}

__device__ __forceinline__ unsigned long long pk2(float lo, float hi) {
    unsigned long long r;
    asm("mov.b64 %0, {%1, %2};" : "=l"(r) : "f"(lo), "f"(hi));
    return r;
}
__device__ __forceinline__ void unpk2(float& lo, float& hi, unsigned long long v) {
    asm("mov.b64 {%0, %1}, %2;" : "=f"(lo), "=f"(hi) : "l"(v));
}
__device__ __forceinline__ unsigned long long ffma2(
    unsigned long long a, unsigned long long b, unsigned long long c) {
    unsigned long long d;
    asm("fma.rn.f32x2 %0, %1, %2, %3;" : "=l"(d) : "l"(a), "l"(b), "l"(c));
    return d;
}

// w = exp(lrelu(a_s + a_d)) = max(exp(as)exp(ad), exp(.2as)exp(.2ad))
__device__ __forceinline__ float wmax(float2 s, float2 d) {
    return fmaxf(s.x * d.x, s.y * d.y);
}

// ---------------------------------------------------------------------------
// K0: edge-index dtype detect (int64 stored little-endian => odd words all 0)
// ---------------------------------------------------------------------------
__global__ void k0_detect(const unsigned int* ei32, int nwords) {
    __shared__ int any_nz;
    if (threadIdx.x == 0) any_nz = 0;
    __syncthreads();
    int samples = 2048;
    if (samples * 2 > nwords) samples = nwords / 2;
    for (int i = threadIdx.x; i < samples; i += 256)
        if (ei32[2 * i + 1] != 0u) any_nz = 1;
    __syncthreads();
    if (threadIdx.x == 0) g_is64 = (any_nz == 0) ? 1 : 0;
}

// ---------------------------------------------------------------------------
// CSR construction (multi-kernel, no grid barrier — proven safe)
// ---------------------------------------------------------------------------
__global__ __launch_bounds__(256) void k_zero(int N) {
    int i = blockIdx.x * 256 + threadIdx.x;
    if (i < N) g_deg[i] = 0;
}

__global__ __launch_bounds__(256) void k_hist(const void* ei, int E) {
    int i = blockIdx.x * 256 + threadIdx.x;
    if (i >= E) return;
    int dst = g_is64 ? (int)((const long long*)ei)[E + i] : ((const int*)ei)[E + i];
    atomicAdd(&g_deg[dst], 1);
}

__global__ __launch_bounds__(512) void k_scan1(int N) {
    __shared__ int wsum[16];
    int i = blockIdx.x * 512 + threadIdx.x;
    int v = (i < N) ? g_deg[i] : 0;
    int lane = threadIdx.x & 31, warp = threadIdx.x >> 5;
    int x = v;
#pragma unroll
    for (int o = 1; o < 32; o <<= 1) {
        int t = __shfl_up_sync(0xffffffffu, x, o);
        if (lane >= o) x += t;
    }
    if (lane == 31) wsum[warp] = x;
    __syncthreads();
    if (warp == 0) {
        int ws = (lane < 16) ? wsum[lane] : 0;
#pragma unroll
        for (int o = 1; o < 16; o <<= 1) {
            int t = __shfl_up_sync(0xffffffffu, ws, o);
            if (lane >= o) ws += t;
        }
        if (lane < 16) wsum[lane] = ws;
    }
    __syncthreads();
    int base = warp ? wsum[warp - 1] : 0;
    if (i < N) g_rowptr[i] = base + x - v;   // exclusive
    if (threadIdx.x == 511) g_blksum[blockIdx.x] = base + x;
}

__global__ __launch_bounds__(256) void k_scan2(int nb) {
    __shared__ int wsum[8];
    int lane = threadIdx.x & 31, warp = threadIdx.x >> 5;
    int v = (threadIdx.x < nb) ? g_blksum[threadIdx.x] : 0;
    int x = v;
#pragma unroll
    for (int o = 1; o < 32; o <<= 1) {
        int t = __shfl_up_sync(0xffffffffu, x, o);
        if (lane >= o) x += t;
    }
    if (lane == 31) wsum[warp] = x;
    __syncthreads();
    if (warp == 0) {
        int ws = (lane < 8) ? wsum[lane] : 0;
#pragma unroll
        for (int o = 1; o < 8; o <<= 1) {
            int t = __shfl_up_sync(0xffffffffu, ws, o);
            if (lane >= o) ws += t;
        }
        if (lane < 8) wsum[lane] = ws;
    }
    __syncthreads();
    int base = warp ? wsum[warp - 1] : 0;
    if (threadIdx.x < nb) g_blksum[threadIdx.x] = base + x - v;   // exclusive
}

__global__ __launch_bounds__(256) void k_scan3(int N) {
    int i = blockIdx.x * 256 + threadIdx.x;
    if (i >= N) return;
    int r = g_rowptr[i] + g_blksum[i >> 9];
    g_rowptr[i] = r;
    g_cursor[i] = r;
}

__global__ __launch_bounds__(256) void k_scatter(const void* ei, int E) {
    int i = blockIdx.x * 256 + threadIdx.x;
    if (i >= E) return;
    int src, dst;
    if (g_is64) {
        src = (int)((const long long*)ei)[i];
        dst = (int)((const long long*)ei)[E + i];
    } else {
        src = ((const int*)ei)[i];
        dst = ((const int*)ei)[E + i];
    }
    int pos = atomicAdd(&g_cursor[dst], 1);
    g_esrc[pos] = src;
}

// ---------------------------------------------------------------------------
// K1 (v3): h1 = x @ W1 outer-product GEMM. Block: 256 thr, 256 nodes x 64
// outs. Thread: 8 nodes x 8 outs (head og). xT staged/transposed in smem with
// register prefetch of the next stage; W resident in smem; f32x2 FMA.
// ---------------------------------------------------------------------------
__global__ __launch_bounds__(256) void k1_gemm_attn(
    const float* __restrict__ x, const float* __restrict__ W1,
    const float* __restrict__ atts, const float* __restrict__ attd, int N)
{
    __shared__ __align__(16) float Ws[IN_F * HC1];   // 32KB, [k][64]
    __shared__ __align__(16) float xT[16 * NPAD];    // 16.6KB, [k%16][node]
    __shared__ float s_as[HC1], s_ad[HC1];
    for (int i = threadIdx.x; i < IN_F * HC1; i += 256) Ws[i] = W1[i];
    if (threadIdx.x < HC1) { s_as[threadIdx.x] = atts[threadIdx.x]; s_ad[threadIdx.x] = attd[threadIdx.x]; }

    const int t  = threadIdx.x;
    const int og = t & 7;          // head / out-group: outs og*8 .. og*8+7
    const int ng = t >> 3;         // node group: nodes ng*8 .. ng*8+7 (0..31)
    const int node_base = blockIdx.x * 256;

    unsigned long long accp[8][4];   // [node][out-pair]
    const unsigned long long Z = pk2(0.f, 0.f);
#pragma unroll
    for (int n = 0; n < 8; n++)
#pragma unroll
        for (int o = 0; o < 4; o++) accp[n][o] = Z;

    // staging: thread t owns node (node_base + t); loads its 16 k per stage.
    const int ld_gn = node_base + t;
    const bool ld_ok = ld_gn < N;
    const float4* xrow = (const float4*)x + (long long)(ld_ok ? ld_gn : 0) * (IN_F / 4);

    float4 v[4];
#pragma unroll
    for (int j = 0; j < 4; j++)
        v[j] = ld_ok ? xrow[j] : make_float4(0.f, 0.f, 0.f, 0.f);

#pragma unroll 1
    for (int ks = 0; ks < 8; ks++) {
        __syncthreads();   // readers of previous stage done
#pragma unroll
        for (int j = 0; j < 4; j++) {
            xT[(j * 4 + 0) * NPAD + t] = v[j].x;
            xT[(j * 4 + 1) * NPAD + t] = v[j].y;
            xT[(j * 4 + 2) * NPAD + t] = v[j].z;
            xT[(j * 4 + 3) * NPAD + t] = v[j].w;
        }
        __syncthreads();
        if (ks < 7) {      // prefetch next stage under the compute below
#pragma unroll
            for (int j = 0; j < 4; j++)
                v[j] = ld_ok ? xrow[(ks + 1) * 4 + j] : make_float4(0.f, 0.f, 0.f, 0.f);
        }

#pragma unroll
        for (int k = 0; k < 16; k++) {
            float4 aA = *(const float4*)&xT[k * NPAD + ng * 8];
            float4 aB = *(const float4*)&xT[k * NPAD + ng * 8 + 4];
            const ulonglong2* bp = (const ulonglong2*)&Ws[(ks * 16 + k) * HC1 + og * 8];
            ulonglong2 b01 = bp[0];
            ulonglong2 b23 = bp[1];
            unsigned long long ap[8];
            ap[0] = pk2(aA.x, aA.x); ap[1] = pk2(aA.y, aA.y);
            ap[2] = pk2(aA.z, aA.z); ap[3] = pk2(aA.w, aA.w);
            ap[4] = pk2(aB.x, aB.x); ap[5] = pk2(aB.y, aB.y);
            ap[6] = pk2(aB.z, aB.z); ap[7] = pk2(aB.w, aB.w);
#pragma unroll
            for (int n = 0; n < 8; n++) {
                accp[n][0] = ffma2(ap[n], b01.x, accp[n][0]);
                accp[n][1] = ffma2(ap[n], b01.y, accp[n][1]);
                accp[n][2] = ffma2(ap[n], b23.x, accp[n][2]);
                accp[n][3] = ffma2(ap[n], b23.y, accp[n][3]);
            }
        }
    }

    // Epilogue: per node, attention dots for head og + fp16 h1 store.
#pragma unroll
    for (int n = 0; n < 8; n++) {
        int node = node_base + ng * 8 + n;
        if (node >= N) break;
        float h[8];
#pragma unroll
        for (int o = 0; o < 4; o++) unpk2(h[2 * o], h[2 * o + 1], accp[n][o]);

        float as = 0.f, ad = 0.f;
#pragma unroll
        for (int c = 0; c < 8; c++) {
            as += h[c] * s_as[og * 8 + c];
            ad += h[c] * s_ad[og * 8 + c];
        }
        g_e1s[node * H1 + og] = make_float2(__expf(as), __expf(NEG_SLOPE * as));
        g_e1d[node * H1 + og] = make_float2(__expf(ad), __expf(NEG_SLOPE * ad));

        union { __half2 hh[4]; uint4 u; } cv;
#pragma unroll
        for (int c = 0; c < 4; c++) cv.hh[c] = __floats2half2_rn(h[2 * c], h[2 * c + 1]);
        *(uint4*)(g_h1h + node * 32 + og * 4) = cv.u;
    }
}

// ---------------------------------------------------------------------------
// KL1: fused layer-1 aggregate (exp-free weights, fp16 payload) + normalize +
//      ELU + h2@W2 + layer-2 exp factors. 8 lanes/node, 32 nodes/block.
// ---------------------------------------------------------------------------
__global__ __launch_bounds__(256) void kL1_gather(
    const float* __restrict__ W2, const float* __restrict__ b1,
    const float* __restrict__ atts2, const float* __restrict__ attd2, int N)
{
    __shared__ float W2s[HC1 * OUT2];   // 10.2KB
    __shared__ float b1s[HC1], as2s[OUT2], ad2s[OUT2];
    for (int i = threadIdx.x; i < HC1 * OUT2; i += 256) W2s[i] = W2[i];
    if (threadIdx.x < HC1) b1s[threadIdx.x] = b1[threadIdx.x];
    if (threadIdx.x < OUT2) { as2s[threadIdx.x] = atts2[threadIdx.x]; ad2s[threadIdx.x] = attd2[threadIdx.x]; }
    __syncthreads();

    const int r = threadIdx.x & 7;
    const int n = blockIdx.x * 32 + (threadIdx.x >> 3);
    const int nc = (n < N) ? n : 0;

    const float2 d12 = g_e1d[nc * H1 + r];   // dst factors, hoisted
    const int beg = g_rowptr[nc];
    const int end = beg + g_deg[nc];

    // self-loop
    float w = wmax(g_e1s[nc * H1 + r], d12);
    float denom = w;
    float acc[8];
    {
        uint4 u = *(const uint4*)(g_h1h + nc * 32 + r * 4);
        float2 f0 = h2f(u.x), f1 = h2f(u.y), f2 = h2f(u.z), f3 = h2f(u.w);
        acc[0] = w * f0.x; acc[1] = w * f0.y; acc[2] = w * f1.x; acc[3] = w * f1.y;
        acc[4] = w * f2.x; acc[5] = w * f2.y; acc[6] = w * f3.x; acc[7] = w * f3.y;
    }

    int p = beg;
    for (; p + 2 <= end; p += 2) {
        int sa = g_esrc[p];
        int sb = g_esrc[p + 1];
        float2 ea = g_e1s[sa * H1 + r];
        float2 eb = g_e1s[sb * H1 + r];
        uint4 ua = *(const uint4*)(g_h1h + sa * 32 + r * 4);
        uint4 ub = *(const uint4*)(g_h1h + sb * 32 + r * 4);
        float wa = wmax(ea, d12);
        float wb = wmax(eb, d12);
        denom += wa + wb;
        float2 f;
        f = h2f(ua.x); acc[0] += wa * f.x; acc[1] += wa * f.y;
        f = h2f(ua.y); acc[2] += wa * f.x; acc[3] += wa * f.y;
        f = h2f(ua.z); acc[4] += wa * f.x; acc[5] += wa * f.y;
        f = h2f(ua.w); acc[6] += wa * f.x; acc[7] += wa * f.y;
        f = h2f(ub.x); acc[0] += wb * f.x; acc[1] += wb * f.y;
        f = h2f(ub.y); acc[2] += wb * f.x; acc[3] += wb * f.y;
        f = h2f(ub.z); acc[4] += wb * f.x; acc[5] += wb * f.y;
        f = h2f(ub.w); acc[6] += wb * f.x; acc[7] += wb * f.y;
    }
    if (p < end) {
        int src = g_esrc[p];
        float wi = wmax(g_e1s[src * H1 + r], d12);
        denom += wi;
        uint4 u = *(const uint4*)(g_h1h + src * 32 + r * 4);
        float2 f;
        f = h2f(u.x); acc[0] += wi * f.x; acc[1] += wi * f.y;
        f = h2f(u.y); acc[2] += wi * f.x; acc[3] += wi * f.y;
        f = h2f(u.z); acc[4] += wi * f.x; acc[5] += wi * f.y;
        f = h2f(u.w); acc[6] += wi * f.x; acc[7] += wi * f.y;
    }

    // h2 = elu(acc/denom + b1)
    float inv = 1.0f / denom;
    float h2r[8];
    {
        const float* bb = &b1s[r * 8];
#pragma unroll
        for (int c = 0; c < 8; c++) {
            float v = acc[c] * inv + bb[c];
            h2r[c] = v > 0.f ? v : expm1f(v);
        }
    }

    // g = h2 @ W2 (width-8 shuffle GEMM); lane r owns cols r, r+8, ..., r+32
    float acc2[5] = {0.f, 0.f, 0.f, 0.f, 0.f};
#pragma unroll
    for (int k = 0; k < HC1; k++) {
        float hk = __shfl_sync(0xffffffffu, h2r[k & 7], k >> 3, 8);
#pragma unroll
        for (int i = 0; i < 5; i++) acc2[i] += hk * W2s[k * OUT2 + r + 8 * i];
    }

    float as = 0.f, ad = 0.f;
#pragma unroll
    for (int i = 0; i < 5; i++) { as += acc2[i] * as2s[r + 8 * i]; ad += acc2[i] * ad2s[r + 8 * i]; }
#pragma unroll
    for (int o = 4; o; o >>= 1) {
        as += __shfl_xor_sync(0xffffffffu, as, o, 8);
        ad += __shfl_xor_sync(0xffffffffu, ad, o, 8);
    }

    // pack g2 to half2: even lane r supplies lo (col r+8i), lane r+1 the hi
    float hi_[5];
#pragma unroll
    for (int i = 0; i < 5; i++) hi_[i] = __shfl_xor_sync(0xffffffffu, acc2[i], 1, 8);

    if (n < N) {
        if (r == 0) {
            g_e2s[n] = make_float2(__expf(as), __expf(NEG_SLOPE * as));
            g_e2d[n] = make_float2(__expf(ad), __expf(NEG_SLOPE * ad));
        }
        if ((r & 1) == 0) {
            __half2* gp = g_g2h + n * 20;
#pragma unroll
            for (int i = 0; i < 5; i++)
                gp[(r >> 1) + 4 * i] = __floats2half2_rn(acc2[i], hi_[i]);
        }
    }
}

// ---------------------------------------------------------------------------
// KL2: fused layer-2 aggregate (exp-free weights, fp16 payload) + normalize +
//      bias + log_softmax. 16 lanes/node; lanes 0..9 own 4 channels.
// ---------------------------------------------------------------------------
__global__ __launch_bounds__(256) void kL2_gather(
    const float* __restrict__ b2, float* __restrict__ out, int N)
{
    const int r = threadIdx.x & 15;
    const int n = blockIdx.x * 16 + (threadIdx.x >> 4);
    const int nc = (n < N) ? n : 0;
    const bool act = (r < 10);

    const float2 dd = g_e2d[nc];   // dst factors, hoisted
    const int beg = g_rowptr[nc];
    const int end = beg + g_deg[nc];

    // self-loop
    float w = wmax(g_e2s[nc], dd);
    float denom = w;
    float4 acc = make_float4(0.f, 0.f, 0.f, 0.f);
    if (act) {
        uint2 u = *(const uint2*)(g_g2h + nc * 20 + r * 2);
        float2 fa = h2f(u.x), fb = h2f(u.y);
        acc = make_float4(w * fa.x, w * fa.y, w * fb.x, w * fb.y);
    }

    int p = beg;
    for (; p + 2 <= end; p += 2) {
        int sa = g_esrc[p];
        int sb = g_esrc[p + 1];
        float2 ea = g_e2s[sa];
        float2 eb = g_e2s[sb];
        uint2 ua = make_uint2(0u, 0u), ub = make_uint2(0u, 0u);
        if (act) {
            ua = *(const uint2*)(g_g2h + sa * 20 + r * 2);
            ub = *(const uint2*)(g_g2h + sb * 20 + r * 2);
        }
        float wa = wmax(ea, dd);
        float wb = wmax(eb, dd);
        denom += wa + wb;
        if (act) {
            float2 f;
            f = h2f(ua.x); acc.x += wa * f.x; acc.y += wa * f.y;
            f = h2f(ua.y); acc.z += wa * f.x; acc.w += wa * f.y;
            f = h2f(ub.x); acc.x += wb * f.x; acc.y += wb * f.y;
            f = h2f(ub.y); acc.z += wb * f.x; acc.w += wb * f.y;
        }
    }
    if (p < end) {
        int src = g_esrc[p];
        float wi = wmax(g_e2s[src], dd);
        denom += wi;
        if (act) {
            uint2 u = *(const uint2*)(g_g2h + src * 20 + r * 2);
            float2 fa = h2f(u.x), fb = h2f(u.y);
            acc.x += wi * fa.x; acc.y += wi * fa.y; acc.z += wi * fb.x; acc.w += wi * fb.y;
        }
    }

    float inv = 1.0f / denom;
    float4 v = make_float4(-3.0e38f, -3.0e38f, -3.0e38f, -3.0e38f);
    if (act) {
        float4 bb = ((const float4*)b2)[r];
        v = make_float4(acc.x * inv + bb.x, acc.y * inv + bb.y,
                        acc.z * inv + bb.z, acc.w * inv + bb.w);
    }

    // log_softmax across the 10 active lanes (width-16 reductions)
    float m = fmaxf(fmaxf(v.x, v.y), fmaxf(v.z, v.w));
#pragma unroll
    for (int o = 8; o; o >>= 1) m = fmaxf(m, __shfl_xor_sync(0xffffffffu, m, o, 16));
    float s = 0.f;
    if (act) s = expf(v.x - m) + expf(v.y - m) + expf(v.z - m) + expf(v.w - m);
#pragma unroll
    for (int o = 8; o; o >>= 1) s += __shfl_xor_sync(0xffffffffu, s, o, 16);
    float lse = m + logf(s);

    if (act && n < N) {
        float4 o4 = make_float4(v.x - lse, v.y - lse, v.z - lse, v.w - lse);
        ((float4*)(out + (long long)n * OUT2))[r] = o4;
    }
}

// ---------------------------------------------------------------------------
extern "C" void kernel_launch(void* const* d_in, const int* in_sizes, int n_in,
                              void* d_out, int out_size)
{
    const float* x     = (const float*)d_in[0];
    const void*  ei    = d_in[1];
    const float* W1    = (const float*)d_in[2];
    const float* atts1 = (const float*)d_in[3];
    const float* attd1 = (const float*)d_in[4];
    const float* b1    = (const float*)d_in[5];
    const float* W2    = (const float*)d_in[6];
    const float* atts2 = (const float*)d_in[7];
    const float* attd2 = (const float*)d_in[8];
    const float* b2    = (const float*)d_in[9];

    int N = in_sizes[0] / IN_F;
    int E = in_sizes[1] / 2;
    if (N > N_CAP) N = N_CAP;
    if (E > E_CAP) E = E_CAP;
    const int nb_scan = (N + 511) / 512;

    // k1 kept at launch index 3 (the slot ncu captures) to verify the retile.
    k_zero<<<(N + 255) / 256, 256>>>(N);                           // 0
    k0_detect<<<1, 256>>>((const unsigned int*)ei, 2 * E);         // 1
    k_hist<<<(E + 255) / 256, 256>>>(ei, E);                       // 2
    k1_gemm_attn<<<(N + 255) / 256, 256>>>(x, W1, atts1, attd1, N);// 3 <- profiled
    k_scan1<<<nb_scan, 512>>>(N);                                  // 4
    k_scan2<<<1, 256>>>(nb_scan);                                  // 5
    k_scan3<<<(N + 255) / 256, 256>>>(N);                          // 6
    k_scatter<<<(E + 255) / 256, 256>>>(ei, E);                    // 7
    kL1_gather<<<(N + 31) / 32, 256>>>(W2, b1, atts2, attd2, N);   // 8
    kL2_gather<<<(N + 15) / 16, 256>>>(b2, (float*)d_out, N);      // 9
}